// round 2
// baseline (speedup 1.0000x reference)
#include <cuda_runtime.h>
#include <math.h>

// Problem dims
#define Bv 64
#define Tv 512
#define Iv 128
#define Hv 1024
#define Gv 4096          // 4*H
#define BTv (Bv*Tv)      // 32768

#define NBLK 128         // persistent-kernel CTA count (all co-resident on 148 SMs)

// ---------------------------------------------------------------------------
// Static device scratch (allocation-free rule: __device__ globals)
// ---------------------------------------------------------------------------
__device__ float g_xg[(size_t)BTv * Gv];   // [B,T,4H] gate pre-activations (both layers reuse)
__device__ float g_h1[(size_t)BTv * Hv];   // layer-0 output sequence [B,T,H]
__device__ float g_h2[(size_t)BTv * Hv];   // layer-1 output sequence [B,T,H]
__device__ float g_WhhT0[Hv * Gv];         // W_hh transposed + gate-interleaved: [k][4j+q]
__device__ float g_WhhT1[Hv * Gv];
__device__ float g_WihT1[Hv * Gv];
__device__ float g_WihT0[Iv * Gv];
__device__ float g_bias0[Gv];              // (b_ih+b_hh), gate-interleaved
__device__ float g_bias1[Gv];

// software grid barrier state
__device__ unsigned g_bar_count = 0;
__device__ volatile unsigned g_bar_gen = 0;

__device__ __forceinline__ void grid_barrier(unsigned& local_gen)
{
    __syncthreads();
    if (threadIdx.x == 0) {
        __threadfence();                       // release: make h writes visible
        unsigned gen = local_gen;
        if (atomicAdd(&g_bar_count, 1u) == NBLK - 1) {
            g_bar_count = 0;
            __threadfence();
            g_bar_gen = gen + 1;               // release all
        } else {
            while (g_bar_gen == gen) { }       // spin (volatile, bypasses L1)
        }
        __threadfence();                       // acquire
    }
    __syncthreads();
    local_gen++;
}

// ---------------------------------------------------------------------------
// Prep: transpose weights to K-major with gate interleave. col = 4*j + q,
// source row = q*H + j  (gate order i,f,g,o).
// ---------------------------------------------------------------------------
__global__ void prep_kernel(const float* __restrict__ Whh0, const float* __restrict__ Whh1,
                            const float* __restrict__ Wih0, const float* __restrict__ Wih1,
                            const float* __restrict__ bih0, const float* __restrict__ bhh0,
                            const float* __restrict__ bih1, const float* __restrict__ bhh1)
{
    size_t stride = (size_t)gridDim.x * blockDim.x;
    size_t tid0 = (size_t)blockIdx.x * blockDim.x + threadIdx.x;

    for (size_t s = tid0; s < (size_t)Gv * Hv; s += stride) {
        int row = (int)(s >> 10);          // q*H + j   (Hv = 1024)
        int k   = (int)(s & 1023);
        int q = row >> 10;
        int j = row & 1023;
        size_t dst = (size_t)k * Gv + 4 * j + q;
        g_WhhT0[dst] = Whh0[s];
        g_WhhT1[dst] = Whh1[s];
        g_WihT1[dst] = Wih1[s];
    }
    for (size_t s = tid0; s < (size_t)Gv * Iv; s += stride) {
        int row = (int)(s >> 7);           // Iv = 128
        int k   = (int)(s & 127);
        int q = row >> 10;
        int j = row & 1023;
        g_WihT0[(size_t)k * Gv + 4 * j + q] = Wih0[s];
    }
    for (size_t s = tid0; s < (size_t)Gv; s += stride) {
        int q = (int)(s >> 10);
        int j = (int)(s & 1023);
        g_bias0[4 * j + q] = bih0[s] + bhh0[s];
        g_bias1[4 * j + q] = bih1[s] + bhh1[s];
    }
}

// ---------------------------------------------------------------------------
// Input projection GEMM: g_xg[bt, c] = bias[c] + sum_k A[bt,k] * WT[k,c]
// Tile: 128 cols x 64 rows per CTA, 256 threads, 32 acc/thread.
// ---------------------------------------------------------------------------
template <int K>
__global__ void proj_kernel(const float* __restrict__ Ax)
{
    const float* __restrict__ A    = (K == Iv) ? Ax : g_h1;
    const float* __restrict__ WT   = (K == Iv) ? g_WihT0 : g_WihT1;
    const float* __restrict__ bias = (K == Iv) ? g_bias0 : g_bias1;

    __shared__ float sA[64][17];

    int g0  = blockIdx.x * 128;
    int bt0 = blockIdx.y * 64;
    int tx = threadIdx.x & 31;   // column group: g = g0 + 4*tx
    int ty = threadIdx.x >> 5;   // row group

    float4 acc[8];
#pragma unroll
    for (int r = 0; r < 8; r++) acc[r] = make_float4(0.f, 0.f, 0.f, 0.f);

    const float* wp = WT + (size_t)g0 + 4 * tx;

    for (int k0 = 0; k0 < K; k0 += 16) {
        __syncthreads();
#pragma unroll
        for (int e = 0; e < 4; e++) {
            int lin = threadIdx.x + 256 * e;
            int r  = lin >> 4;
            int kk = lin & 15;
            sA[r][kk] = A[(size_t)(bt0 + r) * K + k0 + kk];
        }
        __syncthreads();
#pragma unroll
        for (int kk = 0; kk < 16; kk++) {
            float4 w = *(const float4*)(wp + (size_t)(k0 + kk) * Gv);
#pragma unroll
            for (int r = 0; r < 8; r++) {
                float a = sA[ty * 8 + r][kk];
                acc[r].x += w.x * a;
                acc[r].y += w.y * a;
                acc[r].z += w.z * a;
                acc[r].w += w.w * a;
            }
        }
    }

    float4 bv = *(const float4*)&bias[g0 + 4 * tx];
#pragma unroll
    for (int r = 0; r < 8; r++) {
        float4 o;
        o.x = acc[r].x + bv.x;
        o.y = acc[r].y + bv.y;
        o.z = acc[r].z + bv.z;
        o.w = acc[r].w + bv.w;
        *(float4*)&g_xg[(size_t)(bt0 + ty * 8 + r) * Gv + g0 + 4 * tx] = o;
    }
}

// ---------------------------------------------------------------------------
// Persistent per-layer recurrence. One launch handles all T=512 steps via a
// software grid barrier (128 CTAs, all co-resident).
// CTA tile: 32 hidden units (j) x 16 batches. Thread: 1 j x 4 gates x 2 b.
// Cell state lives in registers across all steps.
// ---------------------------------------------------------------------------
__device__ __forceinline__ float sigf(float v) { return 1.0f / (1.0f + expf(-v)); }

__global__ void __launch_bounds__(256, 1)
lstm_layer_kernel(int layer, const float* __restrict__ h0l, const float* __restrict__ c0l)
{
    const float* __restrict__ WT = layer ? g_WhhT1 : g_WhhT0;
    float* __restrict__ hseq     = layer ? g_h2 : g_h1;

    __shared__ float sH[16][33];

    int j0 = (blockIdx.x & 31) * 32;     // 32 j-tiles
    int b0 = (blockIdx.x >> 5) * 16;     // 4 b-tiles of 16
    int tx = threadIdx.x & 31;
    int ty = threadIdx.x >> 5;           // 0..7
    int j  = j0 + tx;
    int bA = b0 + 2 * ty;
    int bB = bA + 1;

    // cell state in registers for the whole sequence
    float cA = c0l[(size_t)bA * Hv + j];
    float cB = c0l[(size_t)bB * Hv + j];

    const float* wp = WT + 4 * (size_t)j;
    unsigned local_gen = g_bar_gen;      // stable at kernel entry

    for (int t = 0; t < Tv; t++) {
        const float* __restrict__ hprev;
        size_t hstride;
        if (t == 0) { hprev = h0l; hstride = Hv; }
        else        { hprev = hseq + (size_t)(t - 1) * Hv; hstride = (size_t)Tv * Hv; }

        float4 accA = *(const float4*)&g_xg[((size_t)bA * Tv + t) * Gv + 4 * j];
        float4 accB = *(const float4*)&g_xg[((size_t)bB * Tv + t) * Gv + 4 * j];

        for (int k0 = 0; k0 < Hv; k0 += 32) {
            __syncthreads();
#pragma unroll
            for (int e = 0; e < 2; e++) {
                int lin = threadIdx.x + 256 * e;
                int bb = lin >> 5;       // 0..15
                int kk = lin & 31;
                sH[bb][kk] = hprev[(size_t)(b0 + bb) * hstride + k0 + kk];
            }
            __syncthreads();
#pragma unroll 8
            for (int kk = 0; kk < 32; kk++) {
                float4 w = *(const float4*)(wp + (size_t)(k0 + kk) * Gv);
                float hA = sH[2 * ty][kk];
                float hB = sH[2 * ty + 1][kk];
                accA.x += w.x * hA; accA.y += w.y * hA; accA.z += w.z * hA; accA.w += w.w * hA;
                accB.x += w.x * hB; accB.y += w.y * hB; accB.z += w.z * hB; accB.w += w.w * hB;
            }
        }

        // epilogue: gate order i, f, g, o == .x, .y, .z, .w
        {
            float i_ = sigf(accA.x), f_ = sigf(accA.y), gg = tanhf(accA.z), o_ = sigf(accA.w);
            cA = f_ * cA + i_ * gg;
            hseq[((size_t)bA * Tv + t) * Hv + j] = o_ * tanhf(cA);
        }
        {
            float i_ = sigf(accB.x), f_ = sigf(accB.y), gg = tanhf(accB.z), o_ = sigf(accB.w);
            cB = f_ * cB + i_ * gg;
            hseq[((size_t)bB * Tv + t) * Hv + j] = o_ * tanhf(cB);
        }

        if (t != Tv - 1) grid_barrier(local_gen);
    }
}

// ---------------------------------------------------------------------------
// Final FC: out[bt] = b_fc + dot(h2[bt,:], W_fc).  One warp per output.
// ---------------------------------------------------------------------------
__global__ void fc_kernel(const float* __restrict__ Wfc, const float* __restrict__ bfc,
                          float* __restrict__ out)
{
    int bt = blockIdx.x * 8 + (threadIdx.x >> 5);
    int lane = threadIdx.x & 31;
    const float* hrow = g_h2 + (size_t)bt * Hv;
    float s = 0.f;
#pragma unroll 8
    for (int k = lane; k < Hv; k += 32) s += hrow[k] * Wfc[k];
#pragma unroll
    for (int off = 16; off; off >>= 1) s += __shfl_down_sync(0xFFFFFFFFu, s, off);
    if (lane == 0) out[bt] = s + bfc[0];
}

// ---------------------------------------------------------------------------
// Launch (6 graph nodes total)
// ---------------------------------------------------------------------------
extern "C" void kernel_launch(void* const* d_in, const int* in_sizes, int n_in,
                              void* d_out, int out_size)
{
    (void)in_sizes; (void)n_in; (void)out_size;
    const float* x    = (const float*)d_in[0];
    const float* h0   = (const float*)d_in[1];   // [2,B,H]
    const float* c0   = (const float*)d_in[2];   // [2,B,H]
    const float* Wih0 = (const float*)d_in[3];
    const float* Whh0 = (const float*)d_in[4];
    const float* bih0 = (const float*)d_in[5];
    const float* bhh0 = (const float*)d_in[6];
    const float* Wih1 = (const float*)d_in[7];
    const float* Whh1 = (const float*)d_in[8];
    const float* bih1 = (const float*)d_in[9];
    const float* bhh1 = (const float*)d_in[10];
    const float* Wfc  = (const float*)d_in[11];
    const float* bfc  = (const float*)d_in[12];
    float* out = (float*)d_out;

    prep_kernel<<<2048, 256>>>(Whh0, Whh1, Wih0, Wih1, bih0, bhh0, bih1, bhh1);

    // Layer 0
    proj_kernel<Iv><<<dim3(Gv / 128, BTv / 64), 256>>>(x);
    lstm_layer_kernel<<<NBLK, 256>>>(0, h0, c0);

    // Layer 1
    proj_kernel<Hv><<<dim3(Gv / 128, BTv / 64), 256>>>(x /*unused; A=g_h1*/);
    lstm_layer_kernel<<<NBLK, 256>>>(1, h0 + (size_t)Bv * Hv, c0 + (size_t)Bv * Hv);

    fc_kernel<<<BTv / 8, 256>>>(Wfc, bfc, out);
}

// round 3
// speedup vs baseline: 1.6885x; 1.6885x over previous
#include <cuda_runtime.h>
#include <math.h>

// Problem dims
#define Bv 64
#define Tv 512
#define Iv 128
#define Hv 1024
#define Gv 4096          // 4*H
#define BTv (Bv*Tv)      // 32768

#define NBLK 128         // persistent CTAs (1/SM, 128 j-tiles of 8)
#define JT 8             // hidden units per CTA

// ---------------------------------------------------------------------------
// Static device scratch
// ---------------------------------------------------------------------------
__device__ float g_xg[(size_t)BTv * Gv];   // [B,T,4H] gate pre-activations
__device__ float g_h1[(size_t)BTv * Hv];   // layer-0 output [B,T,H]
__device__ float g_h2[(size_t)BTv * Hv];   // layer-1 output [B,T,H]
__device__ float g_WhhT0[Hv * Gv];         // W_hh^T, gate-interleaved [k][4j+q]
__device__ float g_WhhT1[Hv * Gv];
__device__ float g_WihT1[Hv * Gv];
__device__ float g_WihT0[Iv * Gv];
__device__ float g_bias0[Gv];
__device__ float g_bias1[Gv];

// software grid barrier
__device__ unsigned g_bar_count = 0;
__device__ volatile unsigned g_bar_gen = 0;

__device__ __forceinline__ void grid_barrier(unsigned& local_gen)
{
    __threadfence();                           // publish this thread's h writes
    __syncthreads();
    if (threadIdx.x == 0) {
        unsigned gen = local_gen;
        if (atomicAdd(&g_bar_count, 1u) == NBLK - 1) {
            g_bar_count = 0;
            __threadfence();
            g_bar_gen = gen + 1;
        } else {
            while (g_bar_gen == gen) { }
        }
        __threadfence();
    }
    __syncthreads();
    local_gen++;
}

// ---------------------------------------------------------------------------
// f32x2 packed-FMA helpers (FFMA2 — only reachable via PTX)
// ---------------------------------------------------------------------------
__device__ __forceinline__ void ffma2(unsigned long long& d,
                                      unsigned long long a, unsigned long long b)
{
    asm("fma.rn.f32x2 %0, %1, %2, %0;" : "+l"(d) : "l"(a), "l"(b));
}
__device__ __forceinline__ unsigned long long f2dup(float x)
{
    unsigned long long r;
    asm("mov.b64 %0, {%1, %1};" : "=l"(r) : "f"(x));
    return r;
}
__device__ __forceinline__ float2 f2unpk(unsigned long long v)
{
    float2 r;
    asm("mov.b64 {%0, %1}, %2;" : "=f"(r.x), "=f"(r.y) : "l"(v));
    return r;
}

// ---------------------------------------------------------------------------
// Prep: transpose weights to K-major with gate interleave (col = 4*j+q).
// ---------------------------------------------------------------------------
__global__ void prep_kernel(const float* __restrict__ Whh0, const float* __restrict__ Whh1,
                            const float* __restrict__ Wih0, const float* __restrict__ Wih1,
                            const float* __restrict__ bih0, const float* __restrict__ bhh0,
                            const float* __restrict__ bih1, const float* __restrict__ bhh1)
{
    size_t stride = (size_t)gridDim.x * blockDim.x;
    size_t tid0 = (size_t)blockIdx.x * blockDim.x + threadIdx.x;

    for (size_t s = tid0; s < (size_t)Gv * Hv; s += stride) {
        int row = (int)(s >> 10);
        int k   = (int)(s & 1023);
        int q = row >> 10;
        int j = row & 1023;
        size_t dst = (size_t)k * Gv + 4 * j + q;
        g_WhhT0[dst] = Whh0[s];
        g_WhhT1[dst] = Whh1[s];
        g_WihT1[dst] = Wih1[s];
    }
    for (size_t s = tid0; s < (size_t)Gv * Iv; s += stride) {
        int row = (int)(s >> 7);
        int k   = (int)(s & 127);
        int q = row >> 10;
        int j = row & 1023;
        g_WihT0[(size_t)k * Gv + 4 * j + q] = Wih0[s];
    }
    for (size_t s = tid0; s < (size_t)Gv; s += stride) {
        int q = (int)(s >> 10);
        int j = (int)(s & 1023);
        g_bias0[4 * j + q] = bih0[s] + bhh0[s];
        g_bias1[4 * j + q] = bih1[s] + bhh1[s];
    }
}

// ---------------------------------------------------------------------------
// Input projection GEMM with f32x2 inner math.
// Tile: 128 cols x 64 rows, 256 threads, 32 acc/thread (16 u64 pairs).
// ---------------------------------------------------------------------------
template <int K>
__global__ void proj_kernel(const float* __restrict__ Ax)
{
    const float* __restrict__ A    = (K == Iv) ? Ax : g_h1;
    const float* __restrict__ WT   = (K == Iv) ? g_WihT0 : g_WihT1;
    const float* __restrict__ bias = (K == Iv) ? g_bias0 : g_bias1;

    __shared__ float sA[64][17];

    int g0  = blockIdx.x * 128;
    int bt0 = blockIdx.y * 64;
    int tx = threadIdx.x & 31;
    int ty = threadIdx.x >> 5;

    unsigned long long a01[8], a23[8];
#pragma unroll
    for (int r = 0; r < 8; r++) { a01[r] = 0ull; a23[r] = 0ull; }

    const float* wp = WT + (size_t)g0 + 4 * tx;

    for (int k0 = 0; k0 < K; k0 += 16) {
        __syncthreads();
#pragma unroll
        for (int e = 0; e < 4; e++) {
            int lin = threadIdx.x + 256 * e;
            int r  = lin >> 4;
            int kk = lin & 15;
            sA[r][kk] = A[(size_t)(bt0 + r) * K + k0 + kk];
        }
        __syncthreads();
#pragma unroll
        for (int kk = 0; kk < 16; kk++) {
            ulonglong2 w = *(const ulonglong2*)(wp + (size_t)(k0 + kk) * Gv);
#pragma unroll
            for (int r = 0; r < 8; r++) {
                unsigned long long da = f2dup(sA[ty * 8 + r][kk]);
                ffma2(a01[r], w.x, da);
                ffma2(a23[r], w.y, da);
            }
        }
    }

    float4 bv = *(const float4*)&bias[g0 + 4 * tx];
#pragma unroll
    for (int r = 0; r < 8; r++) {
        float2 p01 = f2unpk(a01[r]);
        float2 p23 = f2unpk(a23[r]);
        float4 o;
        o.x = p01.x + bv.x;
        o.y = p01.y + bv.y;
        o.z = p23.x + bv.z;
        o.w = p23.y + bv.w;
        *(float4*)&g_xg[(size_t)(bt0 + ty * 8 + r) * Gv + g0 + 4 * tx] = o;
    }
}

// ---------------------------------------------------------------------------
// Persistent recurrence, weight-stationary in SMEM.
// 128 CTAs x 256 threads. CTA: 8 hidden units (j) x all 64 batches.
// Warp w handles j = j0 + w; lane tx handles batches (2tx, 2tx+1).
// W slice (1024k x 32 gate-cols, 128 KB) loaded to SMEM once; h streamed per
// 128-k chunk through a bank-swizzled SMEM tile. Math in f32x2.
// ---------------------------------------------------------------------------
__device__ __forceinline__ float sigf(float v) { return 1.0f / (1.0f + expf(-v)); }

#define SW_ELEMS (1024 * 32)
#define SH_ELEMS (128 * 64)
#define SOUT_ELEMS (64 * 9)
#define SMEM_LSTM ((SW_ELEMS + SH_ELEMS + SOUT_ELEMS) * 4)

__global__ void __launch_bounds__(256, 1)
lstm_layer_kernel(int layer, const float* __restrict__ h0l, const float* __restrict__ c0l)
{
    extern __shared__ float smem[];
    float* sW   = smem;                       // [1024][32]
    float* sH   = sW + SW_ELEMS;              // [128][64], xor-swizzled cols
    float* sOut = sH + SH_ELEMS;              // [64][9]

    const float* __restrict__ WT = layer ? g_WhhT1 : g_WhhT0;
    float* __restrict__ hseq     = layer ? g_h2 : g_h1;

    int tid = threadIdx.x;
    int tx = tid & 31;
    int wj = tid >> 5;            // warp id = local j (0..7)
    int j0 = blockIdx.x * JT;
    int j  = j0 + wj;
    int bA = 2 * tx;
    int bB = 2 * tx + 1;

    // one-time W slice load: coalesced rows of 32 floats
    for (int i = tid; i < SW_ELEMS; i += 256) {
        int k = i >> 5, c = i & 31;
        sW[i] = WT[(size_t)k * Gv + 4 * j0 + c];
    }

    // cell state in registers
    float cA = c0l[(size_t)bA * Hv + j];
    float cB = c0l[(size_t)bB * Hv + j];

    unsigned local_gen = g_bar_gen;

    for (int t = 0; t < Tv; t++) {
        const float* __restrict__ hprev;
        size_t hstride;
        if (t == 0) { hprev = h0l; hstride = Hv; }
        else        { hprev = hseq + (size_t)(t - 1) * Hv; hstride = (size_t)Tv * Hv; }

        // init accumulators from precomputed input projection (+biases)
        ulonglong2 xgA = *(const ulonglong2*)&g_xg[((size_t)bA * Tv + t) * Gv + 4 * j];
        ulonglong2 xgB = *(const ulonglong2*)&g_xg[((size_t)bB * Tv + t) * Gv + 4 * j];
        unsigned long long aA01 = xgA.x, aA23 = xgA.y;
        unsigned long long aB01 = xgB.x, aB23 = xgB.y;

        for (int c = 0; c < 8; c++) {
            int k0c = c * 128;
            __syncthreads();   // previous chunk/step consumers done with sH

            // stage h chunk: warp covers 8 b-rows; coalesced 128B global reads;
            // xor-swizzled smem writes (2-way conflict worst case)
            {
#pragma unroll
                for (int g = 0; g < 2; g++) {
                    int b = wj * 8 + g * 4 + (tx >> 3);
                    const float* hp = hprev + (size_t)b * hstride + k0c;
#pragma unroll
                    for (int i = 0; i < 4; i++) {
                        int kbase = 4 * (tx & 7) + 32 * i;
                        float4 v = *(const float4*)(hp + kbase);
                        float vv[4] = {v.x, v.y, v.z, v.w};
#pragma unroll
                        for (int r = 0; r < 4; r++) {
                            int kk = kbase + r;
                            sH[kk * 64 + (b ^ (2 * (kk & 15)))] = vv[r];
                        }
                    }
                }
            }
            __syncthreads();

            // compute: per kk, W row broadcast (LDS.128), h pair (LDS.64)
            const float* wrow = sW + (size_t)k0c * 32 + 4 * wj;
#pragma unroll 8
            for (int kk = 0; kk < 128; kk++) {
                ulonglong2 w = *(const ulonglong2*)(wrow + kk * 32);
                int e = 2 * (kk & 15);
                float2 h2v = *(const float2*)&sH[kk * 64 + (bA ^ e)];
                unsigned long long dA = f2dup(h2v.x);
                unsigned long long dB = f2dup(h2v.y);
                ffma2(aA01, w.x, dA);
                ffma2(aA23, w.y, dA);
                ffma2(aB01, w.x, dB);
                ffma2(aB23, w.y, dB);
            }
        }

        // epilogue: gates (i,f) = pair01, (g,o) = pair23
        {
            float2 pA01 = f2unpk(aA01), pA23 = f2unpk(aA23);
            float i_ = sigf(pA01.x), f_ = sigf(pA01.y);
            float gg = tanhf(pA23.x), o_ = sigf(pA23.y);
            cA = f_ * cA + i_ * gg;
            sOut[bA * 9 + wj] = o_ * tanhf(cA);
        }
        {
            float2 pB01 = f2unpk(aB01), pB23 = f2unpk(aB23);
            float i_ = sigf(pB01.x), f_ = sigf(pB01.y);
            float gg = tanhf(pB23.x), o_ = sigf(pB23.y);
            cB = f_ * cB + i_ * gg;
            sOut[bB * 9 + wj] = o_ * tanhf(cB);
        }
        __syncthreads();

        // coalesced-ish h write: 32B segment per batch row
        {
            int b = tid >> 2, p = tid & 3;
            float v0 = sOut[b * 9 + 2 * p];
            float v1 = sOut[b * 9 + 2 * p + 1];
            *(float2*)&hseq[((size_t)b * Tv + t) * Hv + j0 + 2 * p] = make_float2(v0, v1);
        }

        if (t != Tv - 1) grid_barrier(local_gen);
    }
}

// ---------------------------------------------------------------------------
// Final FC
// ---------------------------------------------------------------------------
__global__ void fc_kernel(const float* __restrict__ Wfc, const float* __restrict__ bfc,
                          float* __restrict__ out)
{
    int bt = blockIdx.x * 8 + (threadIdx.x >> 5);
    int lane = threadIdx.x & 31;
    const float* hrow = g_h2 + (size_t)bt * Hv;
    float s = 0.f;
#pragma unroll 8
    for (int k = lane; k < Hv; k += 32) s += hrow[k] * Wfc[k];
#pragma unroll
    for (int off = 16; off; off >>= 1) s += __shfl_down_sync(0xFFFFFFFFu, s, off);
    if (lane == 0) out[bt] = s + bfc[0];
}

// ---------------------------------------------------------------------------
// Launch (6 graph nodes)
// ---------------------------------------------------------------------------
extern "C" void kernel_launch(void* const* d_in, const int* in_sizes, int n_in,
                              void* d_out, int out_size)
{
    (void)in_sizes; (void)n_in; (void)out_size;
    const float* x    = (const float*)d_in[0];
    const float* h0   = (const float*)d_in[1];
    const float* c0   = (const float*)d_in[2];
    const float* Wih0 = (const float*)d_in[3];
    const float* Whh0 = (const float*)d_in[4];
    const float* bih0 = (const float*)d_in[5];
    const float* bhh0 = (const float*)d_in[6];
    const float* Wih1 = (const float*)d_in[7];
    const float* Whh1 = (const float*)d_in[8];
    const float* bih1 = (const float*)d_in[9];
    const float* bhh1 = (const float*)d_in[10];
    const float* Wfc  = (const float*)d_in[11];
    const float* bfc  = (const float*)d_in[12];
    float* out = (float*)d_out;

    cudaFuncSetAttribute(lstm_layer_kernel,
                         cudaFuncAttributeMaxDynamicSharedMemorySize, SMEM_LSTM);

    prep_kernel<<<2048, 256>>>(Whh0, Whh1, Wih0, Wih1, bih0, bhh0, bih1, bhh1);

    // Layer 0
    proj_kernel<Iv><<<dim3(Gv / 128, BTv / 64), 256>>>(x);
    lstm_layer_kernel<<<NBLK, 256, SMEM_LSTM>>>(0, h0, c0);

    // Layer 1
    proj_kernel<Hv><<<dim3(Gv / 128, BTv / 64), 256>>>(x);
    lstm_layer_kernel<<<NBLK, 256, SMEM_LSTM>>>(1, h0 + (size_t)Bv * Hv, c0 + (size_t)Bv * Hv);

    fc_kernel<<<BTv / 8, 256>>>(Wfc, bfc, out);
}

// round 4
// speedup vs baseline: 2.1941x; 1.2994x over previous
#include <cuda_runtime.h>
#include <math.h>

// Problem dims
#define Bv 64
#define Tv 512
#define Iv 128
#define Hv 1024
#define Gv 4096          // 4*H
#define BTv (Bv*Tv)      // 32768

#define NBLK 128         // persistent CTAs: 128 j-tiles of 8
#define JT 8             // hidden units per CTA

// ---------------------------------------------------------------------------
// Static device scratch
// ---------------------------------------------------------------------------
__device__ float g_xg[(size_t)BTv * Gv];   // [B,T,4H] gate pre-activations
__device__ float g_h1[(size_t)BTv * Hv];   // layer-0 output [B,T,H]
__device__ float g_h2[(size_t)BTv * Hv];   // layer-1 output [B,T,H]
__device__ float g_WhhT0[Hv * Gv];         // W_hh^T, gate-interleaved [k][4j+q]
__device__ float g_WhhT1[Hv * Gv];
__device__ float g_WihT1[Hv * Gv];
__device__ float g_WihT0[Iv * Gv];
__device__ float g_bias0[Gv];
__device__ float g_bias1[Gv];

// software grid barrier
__device__ unsigned g_bar_count = 0;
__device__ volatile unsigned g_bar_gen = 0;

__device__ __forceinline__ void grid_barrier(unsigned& local_gen)
{
    __threadfence();                           // publish h writes
    __syncthreads();
    if (threadIdx.x == 0) {
        unsigned gen = local_gen;
        if (atomicAdd(&g_bar_count, 1u) == NBLK - 1) {
            g_bar_count = 0;
            __threadfence();
            g_bar_gen = gen + 1;
        } else {
            while (g_bar_gen == gen) { }
        }
        __threadfence();
    }
    __syncthreads();
    local_gen++;
}

// ---------------------------------------------------------------------------
// f32x2 packed helpers
// ---------------------------------------------------------------------------
__device__ __forceinline__ void ffma2(unsigned long long& d,
                                      unsigned long long a, unsigned long long b)
{
    asm("fma.rn.f32x2 %0, %1, %2, %0;" : "+l"(d) : "l"(a), "l"(b));
}
__device__ __forceinline__ unsigned long long addf2(unsigned long long a,
                                                    unsigned long long b)
{
    unsigned long long r;
    asm("add.rn.f32x2 %0, %1, %2;" : "=l"(r) : "l"(a), "l"(b));
    return r;
}
__device__ __forceinline__ unsigned long long f2dup(float x)
{
    unsigned long long r;
    asm("mov.b64 %0, {%1, %1};" : "=l"(r) : "f"(x));
    return r;
}
__device__ __forceinline__ float2 f2unpk(unsigned long long v)
{
    float2 r;
    asm("mov.b64 {%0, %1}, %2;" : "=f"(r.x), "=f"(r.y) : "l"(v));
    return r;
}

// ---------------------------------------------------------------------------
// Prep: transpose weights to K-major with gate interleave (col = 4*j+q).
// ---------------------------------------------------------------------------
__global__ void prep_kernel(const float* __restrict__ Whh0, const float* __restrict__ Whh1,
                            const float* __restrict__ Wih0, const float* __restrict__ Wih1,
                            const float* __restrict__ bih0, const float* __restrict__ bhh0,
                            const float* __restrict__ bih1, const float* __restrict__ bhh1)
{
    size_t stride = (size_t)gridDim.x * blockDim.x;
    size_t tid0 = (size_t)blockIdx.x * blockDim.x + threadIdx.x;

    for (size_t s = tid0; s < (size_t)Gv * Hv; s += stride) {
        int row = (int)(s >> 10);
        int k   = (int)(s & 1023);
        int q = row >> 10;
        int j = row & 1023;
        size_t dst = (size_t)k * Gv + 4 * j + q;
        g_WhhT0[dst] = Whh0[s];
        g_WhhT1[dst] = Whh1[s];
        g_WihT1[dst] = Wih1[s];
    }
    for (size_t s = tid0; s < (size_t)Gv * Iv; s += stride) {
        int row = (int)(s >> 7);
        int k   = (int)(s & 127);
        int q = row >> 10;
        int j = row & 1023;
        g_WihT0[(size_t)k * Gv + 4 * j + q] = Wih0[s];
    }
    for (size_t s = tid0; s < (size_t)Gv; s += stride) {
        int q = (int)(s >> 10);
        int j = (int)(s & 1023);
        g_bias0[4 * j + q] = bih0[s] + bhh0[s];
        g_bias1[4 * j + q] = bih1[s] + bhh1[s];
    }
}

// ---------------------------------------------------------------------------
// Input projection GEMM (unchanged from round 3 — proven)
// ---------------------------------------------------------------------------
template <int K>
__global__ void proj_kernel(const float* __restrict__ Ax)
{
    const float* __restrict__ A    = (K == Iv) ? Ax : g_h1;
    const float* __restrict__ WT   = (K == Iv) ? g_WihT0 : g_WihT1;
    const float* __restrict__ bias = (K == Iv) ? g_bias0 : g_bias1;

    __shared__ float sA[64][17];

    int g0  = blockIdx.x * 128;
    int bt0 = blockIdx.y * 64;
    int tx = threadIdx.x & 31;
    int ty = threadIdx.x >> 5;

    unsigned long long a01[8], a23[8];
#pragma unroll
    for (int r = 0; r < 8; r++) { a01[r] = 0ull; a23[r] = 0ull; }

    const float* wp = WT + (size_t)g0 + 4 * tx;

    for (int k0 = 0; k0 < K; k0 += 16) {
        __syncthreads();
#pragma unroll
        for (int e = 0; e < 4; e++) {
            int lin = threadIdx.x + 256 * e;
            int r  = lin >> 4;
            int kk = lin & 15;
            sA[r][kk] = A[(size_t)(bt0 + r) * K + k0 + kk];
        }
        __syncthreads();
#pragma unroll
        for (int kk = 0; kk < 16; kk++) {
            ulonglong2 w = *(const ulonglong2*)(wp + (size_t)(k0 + kk) * Gv);
#pragma unroll
            for (int r = 0; r < 8; r++) {
                unsigned long long da = f2dup(sA[ty * 8 + r][kk]);
                ffma2(a01[r], w.x, da);
                ffma2(a23[r], w.y, da);
            }
        }
    }

    float4 bv = *(const float4*)&bias[g0 + 4 * tx];
#pragma unroll
    for (int r = 0; r < 8; r++) {
        float2 p01 = f2unpk(a01[r]);
        float2 p23 = f2unpk(a23[r]);
        float4 o;
        o.x = p01.x + bv.x;
        o.y = p01.y + bv.y;
        o.z = p23.x + bv.z;
        o.w = p23.y + bv.w;
        *(float4*)&g_xg[(size_t)(bt0 + ty * 8 + r) * Gv + g0 + 4 * tx] = o;
    }
}

// ---------------------------------------------------------------------------
// Persistent recurrence, J=8 / 8-way k-split.
// 128 CTAs x 256 threads. CTA: 8 j x 64 b.
// Warp w: ALL 8 j, k-range [128w, 128w+128), lane tx: batches (2tx, 2tx+1).
// Per-warp 32-k staging buffer (8 KB) -> no block syncs in mainloop.
// End of step: k-partials reduced via XOR-swizzled smem, epilogue threads own
// (j = tid&7, b = 2*(tid>>3)+{0,1}) with c in registers.
// SMEM: sW 128KB + sHw 64KB (aliased by sRed) + sOut ~2.3KB = 194.3KB.
// ---------------------------------------------------------------------------
__device__ __forceinline__ float sigf(float v) { return 1.0f / (1.0f + expf(-v)); }

#define SW_ELEMS  (1024 * 32)
#define SHW_ELEMS (8 * 2048)          // 8 warps x [32 k][64 b]
#define SOUT_ELEMS (64 * 9)
#define SMEM_LSTM ((SW_ELEMS + SHW_ELEMS + SOUT_ELEMS) * 4)

__global__ void __launch_bounds__(256, 1)
lstm_layer_kernel(int layer, const float* __restrict__ h0l, const float* __restrict__ c0l)
{
    extern __shared__ float smem[];
    float* sW   = smem;                       // [1024][32]
    float* sHw  = sW + SW_ELEMS;              // 8 x [32][64]
    float* sOut = sHw + SHW_ELEMS;            // [64][9]

    const float* __restrict__ WT = layer ? g_WhhT1 : g_WhhT0;
    float* __restrict__ hseq     = layer ? g_h2 : g_h1;

    int tid = threadIdx.x;
    int tx = tid & 31;
    int w  = tid >> 5;                 // warp id 0..7 = k-slice
    int j0 = blockIdx.x * JT;

    // one-time W slice load (coalesced rows of 32 floats)
    for (int i = tid; i < SW_ELEMS; i += 256) {
        int k = i >> 5, c = i & 31;
        sW[i] = WT[(size_t)k * Gv + 4 * j0 + c];
    }
    __syncthreads();

    // epilogue ownership
    int je = tid & 7;                  // local j
    int le = tid >> 3;                 // 0..31
    int be = 2 * le;                   // batch base
    float cA = c0l[(size_t)be * Hv + j0 + je];
    float cB = c0l[(size_t)(be + 1) * Hv + j0 + je];

    int kbase = w * 128;
    float* myH = sHw + w * 2048;
    unsigned long long* myRed = (unsigned long long*)sHw + w * 1024;

    unsigned local_gen = g_bar_gen;

    for (int t = 0; t < Tv; t++) {
        const float* __restrict__ hprev;
        size_t hstride;
        if (t == 0) { hprev = h0l; hstride = Hv; }
        else        { hprev = hseq + (size_t)(t - 1) * Hv; hstride = (size_t)Tv * Hv; }

        // prefetch xg for epilogue cells (consumed after reduction)
        ulonglong2 xgA = *(const ulonglong2*)&g_xg[((size_t)be * Tv + t) * Gv + 4 * (j0 + je)];
        ulonglong2 xgB = *(const ulonglong2*)&g_xg[((size_t)(be + 1) * Tv + t) * Gv + 4 * (j0 + je)];

        // partial accumulators: [j][bl][pair]
        unsigned long long acc[8][2][2];
#pragma unroll
        for (int j = 0; j < 8; j++) {
            acc[j][0][0] = 0ull; acc[j][0][1] = 0ull;
            acc[j][1][0] = 0ull; acc[j][1][1] = 0ull;
        }

        // mainloop over this warp's 128-k range in 32-k chunks
        for (int c2 = 0; c2 < 4; c2++) {
            int k0 = kbase + 32 * c2;
            __syncwarp();
            // stage 64b x 32k into per-warp buffer (swizzled)
#pragma unroll 4
            for (int i = 0; i < 16; i++) {
                int L = 32 * i + tx;
                int b = L >> 3;
                int k4 = (L & 7) * 4;
                float4 v = *(const float4*)(hprev + (size_t)b * hstride + k0 + k4);
                float vv[4] = {v.x, v.y, v.z, v.w};
#pragma unroll
                for (int r = 0; r < 4; r++) {
                    int kkl = k4 + r;
                    myH[kkl * 64 + (b ^ (2 * (kkl & 15)))] = vv[r];
                }
            }
            __syncwarp();
            // compute
#pragma unroll 4
            for (int kkl = 0; kkl < 32; kkl++) {
                float2 hh = *(const float2*)&myH[kkl * 64 + ((2 * tx) ^ (2 * (kkl & 15)))];
                unsigned long long dA = f2dup(hh.x);
                unsigned long long dB = f2dup(hh.y);
                const float* wrow = sW + (size_t)(k0 + kkl) * 32;
#pragma unroll
                for (int j = 0; j < 8; j++) {
                    ulonglong2 wv = *(const ulonglong2*)(wrow + 4 * j);
                    ffma2(acc[j][0][0], wv.x, dA);
                    ffma2(acc[j][0][1], wv.y, dA);
                    ffma2(acc[j][1][0], wv.x, dB);
                    ffma2(acc[j][1][1], wv.y, dB);
                }
            }
        }

        // write partials to own (warp-private) buffer, XOR-swizzled
#pragma unroll
        for (int j = 0; j < 8; j++)
#pragma unroll
            for (int bl = 0; bl < 2; bl++)
#pragma unroll
                for (int p = 0; p < 2; p++) {
                    int local = j * 4 + bl * 2 + p;
                    myRed[tx * 32 + (local ^ tx)] = acc[j][bl][p];
                }
        __syncthreads();

        // reduce 8 k-partials + xg  (thread owns (je, be/be+1))
        unsigned long long s0 = xgA.x, s1 = xgA.y, s2 = xgB.x, s3 = xgB.y;
#pragma unroll
        for (int w2 = 0; w2 < 8; w2++) {
            const unsigned long long* red = (const unsigned long long*)sHw + w2 * 1024;
            int base = le * 32;
            s0 = addf2(s0, red[base + ((je * 4 + 0) ^ le)]);
            s1 = addf2(s1, red[base + ((je * 4 + 1) ^ le)]);
            s2 = addf2(s2, red[base + ((je * 4 + 2) ^ le)]);
            s3 = addf2(s3, red[base + ((je * 4 + 3) ^ le)]);
        }

        // epilogue: pairs (i,f) and (g,o)
        {
            float2 if_ = f2unpk(s0), go = f2unpk(s1);
            float i_ = sigf(if_.x), f_ = sigf(if_.y);
            float gg = tanhf(go.x), o_ = sigf(go.y);
            cA = f_ * cA + i_ * gg;
            sOut[be * 9 + je] = o_ * tanhf(cA);
        }
        {
            float2 if_ = f2unpk(s2), go = f2unpk(s3);
            float i_ = sigf(if_.x), f_ = sigf(if_.y);
            float gg = tanhf(go.x), o_ = sigf(go.y);
            cB = f_ * cB + i_ * gg;
            sOut[(be + 1) * 9 + je] = o_ * tanhf(cB);
        }
        __syncthreads();

        // coalesced-ish h write: float2 per thread
        {
            int b = tid >> 2, p4 = tid & 3;
            float v0 = sOut[b * 9 + 2 * p4];
            float v1 = sOut[b * 9 + 2 * p4 + 1];
            *(float2*)&hseq[((size_t)b * Tv + t) * Hv + j0 + 2 * p4] = make_float2(v0, v1);
        }

        if (t != Tv - 1) grid_barrier(local_gen);
    }
}

// ---------------------------------------------------------------------------
// Final FC
// ---------------------------------------------------------------------------
__global__ void fc_kernel(const float* __restrict__ Wfc, const float* __restrict__ bfc,
                          float* __restrict__ out)
{
    int bt = blockIdx.x * 8 + (threadIdx.x >> 5);
    int lane = threadIdx.x & 31;
    const float* hrow = g_h2 + (size_t)bt * Hv;
    float s = 0.f;
#pragma unroll 8
    for (int k = lane; k < Hv; k += 32) s += hrow[k] * Wfc[k];
#pragma unroll
    for (int off = 16; off; off >>= 1) s += __shfl_down_sync(0xFFFFFFFFu, s, off);
    if (lane == 0) out[bt] = s + bfc[0];
}

// ---------------------------------------------------------------------------
// Launch (6 graph nodes)
// ---------------------------------------------------------------------------
extern "C" void kernel_launch(void* const* d_in, const int* in_sizes, int n_in,
                              void* d_out, int out_size)
{
    (void)in_sizes; (void)n_in; (void)out_size;
    const float* x    = (const float*)d_in[0];
    const float* h0   = (const float*)d_in[1];
    const float* c0   = (const float*)d_in[2];
    const float* Wih0 = (const float*)d_in[3];
    const float* Whh0 = (const float*)d_in[4];
    const float* bih0 = (const float*)d_in[5];
    const float* bhh0 = (const float*)d_in[6];
    const float* Wih1 = (const float*)d_in[7];
    const float* Whh1 = (const float*)d_in[8];
    const float* bih1 = (const float*)d_in[9];
    const float* bhh1 = (const float*)d_in[10];
    const float* Wfc  = (const float*)d_in[11];
    const float* bfc  = (const float*)d_in[12];
    float* out = (float*)d_out;

    cudaFuncSetAttribute(lstm_layer_kernel,
                         cudaFuncAttributeMaxDynamicSharedMemorySize, SMEM_LSTM);

    prep_kernel<<<2048, 256>>>(Whh0, Whh1, Wih0, Wih1, bih0, bhh0, bih1, bhh1);

    // Layer 0
    proj_kernel<Iv><<<dim3(Gv / 128, BTv / 64), 256>>>(x);
    lstm_layer_kernel<<<NBLK, 256, SMEM_LSTM>>>(0, h0, c0);

    // Layer 1
    proj_kernel<Hv><<<dim3(Gv / 128, BTv / 64), 256>>>(x);
    lstm_layer_kernel<<<NBLK, 256, SMEM_LSTM>>>(1, h0 + (size_t)Bv * Hv, c0 + (size_t)Bv * Hv);

    fc_kernel<<<BTv / 8, 256>>>(Wfc, bfc, out);
}

// round 6
// speedup vs baseline: 2.5827x; 1.1771x over previous
#include <cuda_runtime.h>
#include <cuda_bf16.h>
#include <math.h>

// Problem dims
#define Bv 64
#define Tv 512
#define Iv 128
#define Hv 1024
#define Gv 4096          // 4*H
#define BTv (Bv*Tv)      // 32768

#define NBLK 128         // persistent CTAs: 128 j-tiles of 8
#define JT 8             // hidden units per CTA

// ---------------------------------------------------------------------------
// Static device scratch
// ---------------------------------------------------------------------------
__device__ float g_xg[(size_t)BTv * Gv];   // [B,T,4H] gate pre-activations
__device__ float g_h1[(size_t)BTv * Hv];   // layer-0 output [B,T,H]
__device__ float g_h2[(size_t)BTv * Hv];   // layer-1 output [B,T,H]
__device__ float g_WhhT0[Hv * Gv];         // W_hh^T, gate-interleaved [k][4j+q]
__device__ float g_WhhT1[Hv * Gv];
__device__ float g_WihT0[Iv * Gv];
__device__ float g_bias0[Gv];
__device__ float g_bias1[Gv];

// bf16 hi/lo operands for the HMMA proj1 GEMM
__device__ __nv_bfloat16 g_h1bh[(size_t)BTv * Hv];   // A hi  [bt][k]
__device__ __nv_bfloat16 g_h1bl[(size_t)BTv * Hv];   // A lo
__device__ __nv_bfloat16 g_Wbh[(size_t)Gv * Hv];     // B^T hi [interleaved gate c][k]
__device__ __nv_bfloat16 g_Wbl[(size_t)Gv * Hv];     // B^T lo

// software grid barrier
__device__ unsigned g_bar_count = 0;
__device__ volatile unsigned g_bar_gen = 0;

__device__ __forceinline__ void grid_barrier(unsigned& local_gen)
{
    __threadfence();
    __syncthreads();
    if (threadIdx.x == 0) {
        unsigned gen = local_gen;
        if (atomicAdd(&g_bar_count, 1u) == NBLK - 1) {
            g_bar_count = 0;
            __threadfence();
            g_bar_gen = gen + 1;
        } else {
            while (g_bar_gen == gen) { }
        }
        __threadfence();
    }
    __syncthreads();
    local_gen++;
}

// ---------------------------------------------------------------------------
// f32x2 packed helpers
// ---------------------------------------------------------------------------
__device__ __forceinline__ void ffma2(unsigned long long& d,
                                      unsigned long long a, unsigned long long b)
{
    asm("fma.rn.f32x2 %0, %1, %2, %0;" : "+l"(d) : "l"(a), "l"(b));
}
__device__ __forceinline__ unsigned long long addf2(unsigned long long a,
                                                    unsigned long long b)
{
    unsigned long long r;
    asm("add.rn.f32x2 %0, %1, %2;" : "=l"(r) : "l"(a), "l"(b));
    return r;
}
__device__ __forceinline__ unsigned long long f2dup(float x)
{
    unsigned long long r;
    asm("mov.b64 %0, {%1, %1};" : "=l"(r) : "f"(x));
    return r;
}
__device__ __forceinline__ float2 f2unpk(unsigned long long v)
{
    float2 r;
    asm("mov.b64 {%0, %1}, %2;" : "=f"(r.x), "=f"(r.y) : "l"(v));
    return r;
}

// ---------------------------------------------------------------------------
// HMMA / ldmatrix / cp.async helpers (sm_80-class PTX only — no 'a' features)
// ---------------------------------------------------------------------------
__device__ __forceinline__ unsigned smem_u32(const void* p)
{
    unsigned a;
    asm("{ .reg .u64 t; cvta.to.shared.u64 t, %1; cvt.u32.u64 %0, t; }"
        : "=r"(a) : "l"(p));
    return a;
}
__device__ __forceinline__ void ldm_x4(unsigned r[4], unsigned addr)
{
    asm volatile("ldmatrix.sync.aligned.m8n8.x4.shared.b16 {%0,%1,%2,%3}, [%4];"
                 : "=r"(r[0]), "=r"(r[1]), "=r"(r[2]), "=r"(r[3]) : "r"(addr));
}
__device__ __forceinline__ void ldm_x2(unsigned r[2], unsigned addr)
{
    asm volatile("ldmatrix.sync.aligned.m8n8.x2.shared.b16 {%0,%1}, [%2];"
                 : "=r"(r[0]), "=r"(r[1]) : "r"(addr));
}
__device__ __forceinline__ void mma16816(float d[4], const unsigned a[4], const unsigned b[2])
{
    asm volatile("mma.sync.aligned.m16n8k16.row.col.f32.bf16.bf16.f32 "
                 "{%0,%1,%2,%3}, {%4,%5,%6,%7}, {%8,%9}, {%0,%1,%2,%3};"
                 : "+f"(d[0]), "+f"(d[1]), "+f"(d[2]), "+f"(d[3])
                 : "r"(a[0]), "r"(a[1]), "r"(a[2]), "r"(a[3]), "r"(b[0]), "r"(b[1]));
}
__device__ __forceinline__ void cp16(unsigned dst, const void* src)
{
    asm volatile("cp.async.cg.shared.global [%0], [%1], 16;"
                 :: "r"(dst), "l"(src) : "memory");
}
#define CP_COMMIT() asm volatile("cp.async.commit_group;" ::: "memory")
#define CP_WAIT1()  asm volatile("cp.async.wait_group 1;" ::: "memory")
#define CP_WAIT0()  asm volatile("cp.async.wait_group 0;" ::: "memory")

// ---------------------------------------------------------------------------
// Prep: transpose weights K-major + gate interleave; also produce bf16 hi/lo
// of W_ih1 as B^T [c=4j+q][k].
// ---------------------------------------------------------------------------
__global__ void prep_kernel(const float* __restrict__ Whh0, const float* __restrict__ Whh1,
                            const float* __restrict__ Wih0, const float* __restrict__ Wih1,
                            const float* __restrict__ bih0, const float* __restrict__ bhh0,
                            const float* __restrict__ bih1, const float* __restrict__ bhh1)
{
    size_t stride = (size_t)gridDim.x * blockDim.x;
    size_t tid0 = (size_t)blockIdx.x * blockDim.x + threadIdx.x;

    for (size_t s = tid0; s < (size_t)Gv * Hv; s += stride) {
        int row = (int)(s >> 10);
        int k   = (int)(s & 1023);
        int q = row >> 10;
        int j = row & 1023;
        size_t dst = (size_t)k * Gv + 4 * j + q;
        g_WhhT0[dst] = Whh0[s];
        g_WhhT1[dst] = Whh1[s];
        float v = Wih1[s];
        __nv_bfloat16 hi = __float2bfloat16(v);
        float rem = v - __bfloat162float(hi);
        size_t bdst = (size_t)(4 * j + q) * Hv + k;
        g_Wbh[bdst] = hi;
        g_Wbl[bdst] = __float2bfloat16(rem);
    }
    for (size_t s = tid0; s < (size_t)Gv * Iv; s += stride) {
        int row = (int)(s >> 7);
        int k   = (int)(s & 127);
        int q = row >> 10;
        int j = row & 1023;
        g_WihT0[(size_t)k * Gv + 4 * j + q] = Wih0[s];
    }
    for (size_t s = tid0; s < (size_t)Gv; s += stride) {
        int q = (int)(s >> 10);
        int j = (int)(s & 1023);
        g_bias0[4 * j + q] = bih0[s] + bhh0[s];
        g_bias1[4 * j + q] = bih1[s] + bhh1[s];
    }
}

// ---------------------------------------------------------------------------
// proj0: x[32768,128] @ WihT0 -> g_xg (FFMA path, small)
// ---------------------------------------------------------------------------
__global__ void proj0_kernel(const float* __restrict__ A)
{
    const float* __restrict__ WT   = g_WihT0;
    const float* __restrict__ bias = g_bias0;

    __shared__ float sA[64][17];

    int g0  = blockIdx.x * 128;
    int bt0 = blockIdx.y * 64;
    int tx = threadIdx.x & 31;
    int ty = threadIdx.x >> 5;

    unsigned long long a01[8], a23[8];
#pragma unroll
    for (int r = 0; r < 8; r++) { a01[r] = 0ull; a23[r] = 0ull; }

    const float* wp = WT + (size_t)g0 + 4 * tx;

    for (int k0 = 0; k0 < Iv; k0 += 16) {
        __syncthreads();
#pragma unroll
        for (int e = 0; e < 4; e++) {
            int lin = threadIdx.x + 256 * e;
            int r  = lin >> 4;
            int kk = lin & 15;
            sA[r][kk] = A[(size_t)(bt0 + r) * Iv + k0 + kk];
        }
        __syncthreads();
#pragma unroll
        for (int kk = 0; kk < 16; kk++) {
            ulonglong2 w = *(const ulonglong2*)(wp + (size_t)(k0 + kk) * Gv);
#pragma unroll
            for (int r = 0; r < 8; r++) {
                unsigned long long da = f2dup(sA[ty * 8 + r][kk]);
                ffma2(a01[r], w.x, da);
                ffma2(a23[r], w.y, da);
            }
        }
    }

    float4 bv = *(const float4*)&bias[g0 + 4 * tx];
#pragma unroll
    for (int r = 0; r < 8; r++) {
        float2 p01 = f2unpk(a01[r]);
        float2 p23 = f2unpk(a23[r]);
        float4 o;
        o.x = p01.x + bv.x;
        o.y = p01.y + bv.y;
        o.z = p23.x + bv.z;
        o.w = p23.y + bv.w;
        *(float4*)&g_xg[(size_t)(bt0 + ty * 8 + r) * Gv + g0 + 4 * tx] = o;
    }
}

// ---------------------------------------------------------------------------
// h1 (fp32) -> bf16 hi/lo split
// ---------------------------------------------------------------------------
__global__ void h1_split_kernel()
{
    size_t stride = (size_t)gridDim.x * blockDim.x;
    size_t n4 = (size_t)BTv * Hv / 4;
    for (size_t i = (size_t)blockIdx.x * blockDim.x + threadIdx.x; i < n4; i += stride) {
        float4 v = *(const float4*)&g_h1[i * 4];
        float vv[4] = {v.x, v.y, v.z, v.w};
        __nv_bfloat16 hi[4], lo[4];
#pragma unroll
        for (int r = 0; r < 4; r++) {
            hi[r] = __float2bfloat16(vv[r]);
            lo[r] = __float2bfloat16(vv[r] - __bfloat162float(hi[r]));
        }
        *(__nv_bfloat162*)&g_h1bh[i * 4]     = __nv_bfloat162(hi[0], hi[1]);
        *(__nv_bfloat162*)&g_h1bh[i * 4 + 2] = __nv_bfloat162(hi[2], hi[3]);
        *(__nv_bfloat162*)&g_h1bl[i * 4]     = __nv_bfloat162(lo[0], lo[1]);
        *(__nv_bfloat162*)&g_h1bl[i * 4 + 2] = __nv_bfloat162(lo[2], lo[3]);
    }
}

// ---------------------------------------------------------------------------
// proj1 via HMMA (mma.sync m16n8k16 bf16, hi/lo split: Ah*Bh + Ah*Bl + Al*Bh).
// CTA: 128 bt x 128 gates, 8 warps (2m x 4n), warp tile 64x32.
// K chunked by 32, 2-stage cp.async double buffer.
// smem tile rows padded to 40 bf16 (80B) -> conflict-free ldmatrix.
// ---------------------------------------------------------------------------
#define PJ_KC 32
#define PJ_NCHUNK (Hv / PJ_KC)         // 32
#define PJ_ROWB 80                      // bytes per smem row (32 bf16 + pad)
#define PJ_MAT  (128 * PJ_ROWB)         // 10240 B per matrix tile
#define PJ_STAGE (4 * PJ_MAT)           // Ah|Al|Bh|Bl = 40960 B
#define PJ_SMEM  (2 * PJ_STAGE)         // 81920 B

__device__ __forceinline__ void pj_load_chunk(unsigned sbase, int bt0, int n0, int k0, int tid)
{
    // 2048 x 16B transfers, 8 per thread: matrix | row | 16B-chunk
#pragma unroll
    for (int i = 0; i < 8; i++) {
        int u = tid + 256 * i;
        int mat = u >> 9;            // 0..3
        int rr  = (u >> 2) & 127;
        int cc  = u & 3;
        unsigned dst = sbase + mat * PJ_MAT + rr * PJ_ROWB + cc * 16;
        const __nv_bfloat16* src;
        if      (mat == 0) src = g_h1bh + (size_t)(bt0 + rr) * Hv + k0 + cc * 8;
        else if (mat == 1) src = g_h1bl + (size_t)(bt0 + rr) * Hv + k0 + cc * 8;
        else if (mat == 2) src = g_Wbh  + (size_t)(n0  + rr) * Hv + k0 + cc * 8;
        else               src = g_Wbl  + (size_t)(n0  + rr) * Hv + k0 + cc * 8;
        cp16(dst, src);
    }
}

__global__ void __launch_bounds__(256, 1)
proj1_mma_kernel()
{
    extern __shared__ char dsm[];
    unsigned sb0 = smem_u32(dsm);

    __shared__ float s_bias[128];

    int tid  = threadIdx.x;
    int lane = tid & 31;
    int w    = tid >> 5;           // 0..7
    int wm   = w & 1;              // m-half
    int wn   = w >> 1;             // 0..3 n-quarter
    int n0   = blockIdx.x * 128;
    int bt0  = blockIdx.y * 128;

    for (int i = tid; i < 128; i += 256) s_bias[i] = g_bias1[n0 + i];

    float acc[4][4][4];
#pragma unroll
    for (int mf = 0; mf < 4; mf++)
#pragma unroll
        for (int nf = 0; nf < 4; nf++)
#pragma unroll
            for (int e = 0; e < 4; e++) acc[mf][nf][e] = 0.f;

    // per-lane ldmatrix byte offsets within a matrix tile
    // A x4: row = 64*wm + 16*mf + (lane&15); col8 = (lane&16) ? 8 : 0
    unsigned aoff = (unsigned)((64 * wm + (lane & 15)) * PJ_ROWB + ((lane & 16) ? 16 : 0));
    // B x2: rl = lane&15; row = 32*wn + 8*nf + (rl&7); col8 = (rl&8)?8:0
    int rl = lane & 15;
    unsigned boff = (unsigned)((32 * wn + (rl & 7)) * PJ_ROWB + ((rl & 8) ? 16 : 0));

    // prologue
    pj_load_chunk(sb0,            bt0, n0, 0,     tid); CP_COMMIT();
    pj_load_chunk(sb0 + PJ_STAGE, bt0, n0, PJ_KC, tid); CP_COMMIT();

    for (int c = 0; c < PJ_NCHUNK; c++) {
        unsigned sb = sb0 + (c & 1) * PJ_STAGE;
        if (c < PJ_NCHUNK - 1) { CP_WAIT1(); } else { CP_WAIT0(); }
        __syncthreads();

#pragma unroll
        for (int ks = 0; ks < 2; ks++) {
            unsigned kb = (unsigned)(ks * 32);   // 16 bf16 = 32 bytes
            unsigned Ah[4][4], Al[4][4], Bh[4][2], Bl[4][2];
#pragma unroll
            for (int mf = 0; mf < 4; mf++) {
                unsigned ra = sb + aoff + kb + (unsigned)(16 * mf * PJ_ROWB);
                ldm_x4(Ah[mf], ra);
                ldm_x4(Al[mf], ra + PJ_MAT);
            }
#pragma unroll
            for (int nf = 0; nf < 4; nf++) {
                unsigned rb = sb + 2 * PJ_MAT + boff + kb + (unsigned)(8 * nf * PJ_ROWB);
                ldm_x2(Bh[nf], rb);
                ldm_x2(Bl[nf], rb + PJ_MAT);
            }
#pragma unroll
            for (int mf = 0; mf < 4; mf++)
#pragma unroll
                for (int nf = 0; nf < 4; nf++) {
                    mma16816(acc[mf][nf], Ah[mf], Bh[nf]);
                    mma16816(acc[mf][nf], Ah[mf], Bl[nf]);
                    mma16816(acc[mf][nf], Al[mf], Bh[nf]);
                }
        }

        __syncthreads();   // all warps done reading this buffer
        if (c + 2 < PJ_NCHUNK) {
            pj_load_chunk(sb, bt0, n0, (c + 2) * PJ_KC, tid);
            CP_COMMIT();
        }
    }

    // epilogue: frag (mf,nf): rows bt0+64wm+16mf+lane/4 (+8), cols n0+32wn+8nf+2*(lane%4)
    int mrow = bt0 + 64 * wm + (lane >> 2);
    int ncol = 32 * wn + 2 * (lane & 3);
#pragma unroll
    for (int mf = 0; mf < 4; mf++) {
#pragma unroll
        for (int nf = 0; nf < 4; nf++) {
            int cc = ncol + 8 * nf;
            float b0 = s_bias[cc], b1 = s_bias[cc + 1];
            float* p0 = &g_xg[(size_t)(mrow + 16 * mf) * Gv + n0 + cc];
            float* p1 = &g_xg[(size_t)(mrow + 16 * mf + 8) * Gv + n0 + cc];
            *(float2*)p0 = make_float2(acc[mf][nf][0] + b0, acc[mf][nf][1] + b1);
            *(float2*)p1 = make_float2(acc[mf][nf][2] + b0, acc[mf][nf][3] + b1);
        }
    }
}

// ---------------------------------------------------------------------------
// Persistent recurrence (unchanged from round 4 — proven)
// ---------------------------------------------------------------------------
__device__ __forceinline__ float sigf(float v) { return 1.0f / (1.0f + expf(-v)); }

#define SW_ELEMS  (1024 * 32)
#define SHW_ELEMS (8 * 2048)
#define SOUT_ELEMS (64 * 9)
#define SMEM_LSTM ((SW_ELEMS + SHW_ELEMS + SOUT_ELEMS) * 4)

__global__ void __launch_bounds__(256, 1)
lstm_layer_kernel(int layer, const float* __restrict__ h0l, const float* __restrict__ c0l)
{
    extern __shared__ float smem[];
    float* sW   = smem;
    float* sHw  = sW + SW_ELEMS;
    float* sOut = sHw + SHW_ELEMS;

    const float* __restrict__ WT = layer ? g_WhhT1 : g_WhhT0;
    float* __restrict__ hseq     = layer ? g_h2 : g_h1;

    int tid = threadIdx.x;
    int tx = tid & 31;
    int w  = tid >> 5;
    int j0 = blockIdx.x * JT;

    for (int i = tid; i < SW_ELEMS; i += 256) {
        int k = i >> 5, c = i & 31;
        sW[i] = WT[(size_t)k * Gv + 4 * j0 + c];
    }
    __syncthreads();

    int je = tid & 7;
    int le = tid >> 3;
    int be = 2 * le;
    float cA = c0l[(size_t)be * Hv + j0 + je];
    float cB = c0l[(size_t)(be + 1) * Hv + j0 + je];

    int kbase = w * 128;
    float* myH = sHw + w * 2048;
    unsigned long long* myRed = (unsigned long long*)sHw + w * 1024;

    unsigned local_gen = g_bar_gen;

    for (int t = 0; t < Tv; t++) {
        const float* __restrict__ hprev;
        size_t hstride;
        if (t == 0) { hprev = h0l; hstride = Hv; }
        else        { hprev = hseq + (size_t)(t - 1) * Hv; hstride = (size_t)Tv * Hv; }

        ulonglong2 xgA = *(const ulonglong2*)&g_xg[((size_t)be * Tv + t) * Gv + 4 * (j0 + je)];
        ulonglong2 xgB = *(const ulonglong2*)&g_xg[((size_t)(be + 1) * Tv + t) * Gv + 4 * (j0 + je)];

        unsigned long long acc[8][2][2];
#pragma unroll
        for (int j = 0; j < 8; j++) {
            acc[j][0][0] = 0ull; acc[j][0][1] = 0ull;
            acc[j][1][0] = 0ull; acc[j][1][1] = 0ull;
        }

        for (int c2 = 0; c2 < 4; c2++) {
            int k0 = kbase + 32 * c2;
            __syncwarp();
#pragma unroll 4
            for (int i = 0; i < 16; i++) {
                int L = 32 * i + tx;
                int b = L >> 3;
                int k4 = (L & 7) * 4;
                float4 v = *(const float4*)(hprev + (size_t)b * hstride + k0 + k4);
                float vv[4] = {v.x, v.y, v.z, v.w};
#pragma unroll
                for (int r = 0; r < 4; r++) {
                    int kkl = k4 + r;
                    myH[kkl * 64 + (b ^ (2 * (kkl & 15)))] = vv[r];
                }
            }
            __syncwarp();
#pragma unroll 4
            for (int kkl = 0; kkl < 32; kkl++) {
                float2 hh = *(const float2*)&myH[kkl * 64 + ((2 * tx) ^ (2 * (kkl & 15)))];
                unsigned long long dA = f2dup(hh.x);
                unsigned long long dB = f2dup(hh.y);
                const float* wrow = sW + (size_t)(k0 + kkl) * 32;
#pragma unroll
                for (int j = 0; j < 8; j++) {
                    ulonglong2 wv = *(const ulonglong2*)(wrow + 4 * j);
                    ffma2(acc[j][0][0], wv.x, dA);
                    ffma2(acc[j][0][1], wv.y, dA);
                    ffma2(acc[j][1][0], wv.x, dB);
                    ffma2(acc[j][1][1], wv.y, dB);
                }
            }
        }

#pragma unroll
        for (int j = 0; j < 8; j++)
#pragma unroll
            for (int bl = 0; bl < 2; bl++)
#pragma unroll
                for (int p = 0; p < 2; p++) {
                    int local = j * 4 + bl * 2 + p;
                    myRed[tx * 32 + (local ^ tx)] = acc[j][bl][p];
                }
        __syncthreads();

        unsigned long long s0 = xgA.x, s1 = xgA.y, s2 = xgB.x, s3 = xgB.y;
#pragma unroll
        for (int w2 = 0; w2 < 8; w2++) {
            const unsigned long long* red = (const unsigned long long*)sHw + w2 * 1024;
            int base = le * 32;
            s0 = addf2(s0, red[base + ((je * 4 + 0) ^ le)]);
            s1 = addf2(s1, red[base + ((je * 4 + 1) ^ le)]);
            s2 = addf2(s2, red[base + ((je * 4 + 2) ^ le)]);
            s3 = addf2(s3, red[base + ((je * 4 + 3) ^ le)]);
        }

        {
            float2 if_ = f2unpk(s0), go = f2unpk(s1);
            float i_ = sigf(if_.x), f_ = sigf(if_.y);
            float gg = tanhf(go.x), o_ = sigf(go.y);
            cA = f_ * cA + i_ * gg;
            sOut[be * 9 + je] = o_ * tanhf(cA);
        }
        {
            float2 if_ = f2unpk(s2), go = f2unpk(s3);
            float i_ = sigf(if_.x), f_ = sigf(if_.y);
            float gg = tanhf(go.x), o_ = sigf(go.y);
            cB = f_ * cB + i_ * gg;
            sOut[(be + 1) * 9 + je] = o_ * tanhf(cB);
        }
        __syncthreads();

        {
            int b = tid >> 2, p4 = tid & 3;
            float v0 = sOut[b * 9 + 2 * p4];
            float v1 = sOut[b * 9 + 2 * p4 + 1];
            *(float2*)&hseq[((size_t)b * Tv + t) * Hv + j0 + 2 * p4] = make_float2(v0, v1);
        }

        if (t != Tv - 1) grid_barrier(local_gen);
    }
}

// ---------------------------------------------------------------------------
// Final FC
// ---------------------------------------------------------------------------
__global__ void fc_kernel(const float* __restrict__ Wfc, const float* __restrict__ bfc,
                          float* __restrict__ out)
{
    int bt = blockIdx.x * 8 + (threadIdx.x >> 5);
    int lane = threadIdx.x & 31;
    const float* hrow = g_h2 + (size_t)bt * Hv;
    float s = 0.f;
#pragma unroll 8
    for (int k = lane; k < Hv; k += 32) s += hrow[k] * Wfc[k];
#pragma unroll
    for (int off = 16; off; off >>= 1) s += __shfl_down_sync(0xFFFFFFFFu, s, off);
    if (lane == 0) out[bt] = s + bfc[0];
}

// ---------------------------------------------------------------------------
// Launch (7 graph nodes)
// ---------------------------------------------------------------------------
extern "C" void kernel_launch(void* const* d_in, const int* in_sizes, int n_in,
                              void* d_out, int out_size)
{
    (void)in_sizes; (void)n_in; (void)out_size;
    const float* x    = (const float*)d_in[0];
    const float* h0   = (const float*)d_in[1];
    const float* c0   = (const float*)d_in[2];
    const float* Wih0 = (const float*)d_in[3];
    const float* Whh0 = (const float*)d_in[4];
    const float* bih0 = (const float*)d_in[5];
    const float* bhh0 = (const float*)d_in[6];
    const float* Wih1 = (const float*)d_in[7];
    const float* Whh1 = (const float*)d_in[8];
    const float* bih1 = (const float*)d_in[9];
    const float* bhh1 = (const float*)d_in[10];
    const float* Wfc  = (const float*)d_in[11];
    const float* bfc  = (const float*)d_in[12];
    float* out = (float*)d_out;

    cudaFuncSetAttribute(lstm_layer_kernel,
                         cudaFuncAttributeMaxDynamicSharedMemorySize, SMEM_LSTM);
    cudaFuncSetAttribute(proj1_mma_kernel,
                         cudaFuncAttributeMaxDynamicSharedMemorySize, PJ_SMEM);

    prep_kernel<<<2048, 256>>>(Whh0, Whh1, Wih0, Wih1, bih0, bhh0, bih1, bhh1);

    // Layer 0
    proj0_kernel<<<dim3(Gv / 128, BTv / 64), 256>>>(x);
    lstm_layer_kernel<<<NBLK, 256, SMEM_LSTM>>>(0, h0, c0);

    // Layer 1: bf16 split + HMMA projection
    h1_split_kernel<<<2048, 256>>>();
    proj1_mma_kernel<<<dim3(Gv / 128, BTv / 128), 256, PJ_SMEM>>>();
    lstm_layer_kernel<<<NBLK, 256, SMEM_LSTM>>>(1, h0 + (size_t)Bv * Hv, c0 + (size_t)Bv * Hv);

    fc_kernel<<<BTv / 8, 256>>>(Wfc, bfc, out);
}

// round 7
// speedup vs baseline: 3.4099x; 1.3203x over previous
#include <cuda_runtime.h>
#include <cuda_bf16.h>
#include <math.h>

// Problem dims
#define Bv 64
#define Tv 512
#define Iv 128
#define Hv 1024
#define Gv 4096          // 4*H
#define BTv (Bv*Tv)      // 32768

#define NBLK 128         // persistent CTAs for recurrence

// ---------------------------------------------------------------------------
// Static device scratch
// ---------------------------------------------------------------------------
__device__ float g_xg[(size_t)BTv * Gv];       // [B,T,4H] gate pre-activations
__device__ float g_h2[(size_t)BTv * Hv];       // layer-1 output fp32 (for fc)
__device__ float g_WihT0[Iv * Gv];
__device__ float g_bias0[Gv];
__device__ float g_bias1[Gv];

// bf16 hi/lo h sequences (written by recurrence epilogues)
__device__ __nv_bfloat16 g_h1bh[(size_t)BTv * Hv];
__device__ __nv_bfloat16 g_h1bl[(size_t)BTv * Hv];
__device__ __nv_bfloat16 g_h2bh[(size_t)BTv * Hv];
__device__ __nv_bfloat16 g_h2bl[(size_t)BTv * Hv];

// bf16 hi/lo weights, [c = 4j+q][k] layout
__device__ __nv_bfloat16 g_Wbh[(size_t)Gv * Hv];     // W_ih1 (proj1 B)
__device__ __nv_bfloat16 g_Wbl[(size_t)Gv * Hv];
__device__ __nv_bfloat16 g_Whh0bh[(size_t)Gv * Hv];  // W_hh0
__device__ __nv_bfloat16 g_Whh0bl[(size_t)Gv * Hv];
__device__ __nv_bfloat16 g_Whh1bh[(size_t)Gv * Hv];  // W_hh1
__device__ __nv_bfloat16 g_Whh1bl[(size_t)Gv * Hv];

// h0 bf16 hi/lo split: [2][64][1024]
__device__ __nv_bfloat16 g_h0sh[2 * Bv * Hv];
__device__ __nv_bfloat16 g_h0sl[2 * Bv * Hv];

// software grid barrier
__device__ unsigned g_bar_count = 0;
__device__ volatile unsigned g_bar_gen = 0;

__device__ __forceinline__ void grid_barrier(unsigned& local_gen)
{
    __threadfence();
    __syncthreads();
    if (threadIdx.x == 0) {
        unsigned gen = local_gen;
        if (atomicAdd(&g_bar_count, 1u) == NBLK - 1) {
            g_bar_count = 0;
            __threadfence();
            g_bar_gen = gen + 1;
        } else {
            while (g_bar_gen == gen) { }
        }
        __threadfence();
    }
    __syncthreads();
    local_gen++;
}

// ---------------------------------------------------------------------------
// f32x2 packed helpers (proj0)
// ---------------------------------------------------------------------------
__device__ __forceinline__ void ffma2(unsigned long long& d,
                                      unsigned long long a, unsigned long long b)
{
    asm("fma.rn.f32x2 %0, %1, %2, %0;" : "+l"(d) : "l"(a), "l"(b));
}
__device__ __forceinline__ unsigned long long f2dup(float x)
{
    unsigned long long r;
    asm("mov.b64 %0, {%1, %1};" : "=l"(r) : "f"(x));
    return r;
}
__device__ __forceinline__ float2 f2unpk(unsigned long long v)
{
    float2 r;
    asm("mov.b64 {%0, %1}, %2;" : "=f"(r.x), "=f"(r.y) : "l"(v));
    return r;
}

// ---------------------------------------------------------------------------
// HMMA / ldmatrix / cp.async helpers
// ---------------------------------------------------------------------------
__device__ __forceinline__ unsigned smem_u32(const void* p)
{
    unsigned a;
    asm("{ .reg .u64 t; cvta.to.shared.u64 t, %1; cvt.u32.u64 %0, t; }"
        : "=r"(a) : "l"(p));
    return a;
}
__device__ __forceinline__ void ldm_x4(unsigned r[4], unsigned addr)
{
    asm volatile("ldmatrix.sync.aligned.m8n8.x4.shared.b16 {%0,%1,%2,%3}, [%4];"
                 : "=r"(r[0]), "=r"(r[1]), "=r"(r[2]), "=r"(r[3]) : "r"(addr));
}
__device__ __forceinline__ void ldm_x2(unsigned r[2], unsigned addr)
{
    asm volatile("ldmatrix.sync.aligned.m8n8.x2.shared.b16 {%0,%1}, [%2];"
                 : "=r"(r[0]), "=r"(r[1]) : "r"(addr));
}
__device__ __forceinline__ void mma16816(float d[4], const unsigned a[4], const unsigned b[2])
{
    asm volatile("mma.sync.aligned.m16n8k16.row.col.f32.bf16.bf16.f32 "
                 "{%0,%1,%2,%3}, {%4,%5,%6,%7}, {%8,%9}, {%0,%1,%2,%3};"
                 : "+f"(d[0]), "+f"(d[1]), "+f"(d[2]), "+f"(d[3])
                 : "r"(a[0]), "r"(a[1]), "r"(a[2]), "r"(a[3]), "r"(b[0]), "r"(b[1]));
}
__device__ __forceinline__ void cp16(unsigned dst, const void* src)
{
    asm volatile("cp.async.cg.shared.global [%0], [%1], 16;"
                 :: "r"(dst), "l"(src) : "memory");
}
#define CP_COMMIT() asm volatile("cp.async.commit_group;" ::: "memory")
#define CP_WAIT1()  asm volatile("cp.async.wait_group 1;" ::: "memory")
#define CP_WAIT0()  asm volatile("cp.async.wait_group 0;" ::: "memory")

__device__ __forceinline__ float sigf(float v) { return 1.0f / (1.0f + expf(-v)); }

// ---------------------------------------------------------------------------
// Prep: all weight transforms + h0 split.
// ---------------------------------------------------------------------------
__global__ void prep_kernel(const float* __restrict__ Whh0, const float* __restrict__ Whh1,
                            const float* __restrict__ Wih0, const float* __restrict__ Wih1,
                            const float* __restrict__ bih0, const float* __restrict__ bhh0,
                            const float* __restrict__ bih1, const float* __restrict__ bhh1,
                            const float* __restrict__ h0)
{
    size_t stride = (size_t)gridDim.x * blockDim.x;
    size_t tid0 = (size_t)blockIdx.x * blockDim.x + threadIdx.x;

    for (size_t s = tid0; s < (size_t)Gv * Hv; s += stride) {
        int row = (int)(s >> 10);
        int k   = (int)(s & 1023);
        int q = row >> 10;
        int j = row & 1023;
        size_t bdst = (size_t)(4 * j + q) * Hv + k;

        float v = Whh0[s];
        __nv_bfloat16 hi = __float2bfloat16(v);
        g_Whh0bh[bdst] = hi;
        g_Whh0bl[bdst] = __float2bfloat16(v - __bfloat162float(hi));

        v = Whh1[s];
        hi = __float2bfloat16(v);
        g_Whh1bh[bdst] = hi;
        g_Whh1bl[bdst] = __float2bfloat16(v - __bfloat162float(hi));

        v = Wih1[s];
        hi = __float2bfloat16(v);
        g_Wbh[bdst] = hi;
        g_Wbl[bdst] = __float2bfloat16(v - __bfloat162float(hi));
    }
    for (size_t s = tid0; s < (size_t)Gv * Iv; s += stride) {
        int row = (int)(s >> 7);
        int k   = (int)(s & 127);
        int q = row >> 10;
        int j = row & 1023;
        g_WihT0[(size_t)k * Gv + 4 * j + q] = Wih0[s];
    }
    for (size_t s = tid0; s < (size_t)Gv; s += stride) {
        int q = (int)(s >> 10);
        int j = (int)(s & 1023);
        g_bias0[4 * j + q] = bih0[s] + bhh0[s];
        g_bias1[4 * j + q] = bih1[s] + bhh1[s];
    }
    for (size_t s = tid0; s < (size_t)2 * Bv * Hv; s += stride) {
        float v = h0[s];
        __nv_bfloat16 hi = __float2bfloat16(v);
        g_h0sh[s] = hi;
        g_h0sl[s] = __float2bfloat16(v - __bfloat162float(hi));
    }
}

// ---------------------------------------------------------------------------
// proj0: x[32768,128] @ WihT0 -> g_xg (FFMA path, small)
// ---------------------------------------------------------------------------
__global__ void proj0_kernel(const float* __restrict__ A)
{
    const float* __restrict__ WT   = g_WihT0;
    const float* __restrict__ bias = g_bias0;

    __shared__ float sA[64][17];

    int g0  = blockIdx.x * 128;
    int bt0 = blockIdx.y * 64;
    int tx = threadIdx.x & 31;
    int ty = threadIdx.x >> 5;

    unsigned long long a01[8], a23[8];
#pragma unroll
    for (int r = 0; r < 8; r++) { a01[r] = 0ull; a23[r] = 0ull; }

    const float* wp = WT + (size_t)g0 + 4 * tx;

    for (int k0 = 0; k0 < Iv; k0 += 16) {
        __syncthreads();
#pragma unroll
        for (int e = 0; e < 4; e++) {
            int lin = threadIdx.x + 256 * e;
            int r  = lin >> 4;
            int kk = lin & 15;
            sA[r][kk] = A[(size_t)(bt0 + r) * Iv + k0 + kk];
        }
        __syncthreads();
#pragma unroll
        for (int kk = 0; kk < 16; kk++) {
            ulonglong2 w = *(const ulonglong2*)(wp + (size_t)(k0 + kk) * Gv);
#pragma unroll
            for (int r = 0; r < 8; r++) {
                unsigned long long da = f2dup(sA[ty * 8 + r][kk]);
                ffma2(a01[r], w.x, da);
                ffma2(a23[r], w.y, da);
            }
        }
    }

    float4 bv = *(const float4*)&bias[g0 + 4 * tx];
#pragma unroll
    for (int r = 0; r < 8; r++) {
        float2 p01 = f2unpk(a01[r]);
        float2 p23 = f2unpk(a23[r]);
        float4 o;
        o.x = p01.x + bv.x;
        o.y = p01.y + bv.y;
        o.z = p23.x + bv.z;
        o.w = p23.y + bv.w;
        *(float4*)&g_xg[(size_t)(bt0 + ty * 8 + r) * Gv + g0 + 4 * tx] = o;
    }
}

// ---------------------------------------------------------------------------
// proj1 via HMMA (unchanged structure from round 6 — proven)
// ---------------------------------------------------------------------------
#define PJ_KC 32
#define PJ_NCHUNK (Hv / PJ_KC)
#define PJ_ROWB 80
#define PJ_MAT  (128 * PJ_ROWB)
#define PJ_STAGE (4 * PJ_MAT)
#define PJ_SMEM  (2 * PJ_STAGE)

__device__ __forceinline__ void pj_load_chunk(unsigned sbase, int bt0, int n0, int k0, int tid)
{
#pragma unroll
    for (int i = 0; i < 8; i++) {
        int u = tid + 256 * i;
        int mat = u >> 9;
        int rr  = (u >> 2) & 127;
        int cc  = u & 3;
        unsigned dst = sbase + mat * PJ_MAT + rr * PJ_ROWB + cc * 16;
        const __nv_bfloat16* src;
        if      (mat == 0) src = g_h1bh + (size_t)(bt0 + rr) * Hv + k0 + cc * 8;
        else if (mat == 1) src = g_h1bl + (size_t)(bt0 + rr) * Hv + k0 + cc * 8;
        else if (mat == 2) src = g_Wbh  + (size_t)(n0  + rr) * Hv + k0 + cc * 8;
        else               src = g_Wbl  + (size_t)(n0  + rr) * Hv + k0 + cc * 8;
        cp16(dst, src);
    }
}

__global__ void __launch_bounds__(256, 1)
proj1_mma_kernel()
{
    extern __shared__ char dsm[];
    unsigned sb0 = smem_u32(dsm);

    __shared__ float s_bias[128];

    int tid  = threadIdx.x;
    int lane = tid & 31;
    int w    = tid >> 5;
    int wm   = w & 1;
    int wn   = w >> 1;
    int n0   = blockIdx.x * 128;
    int bt0  = blockIdx.y * 128;

    for (int i = tid; i < 128; i += 256) s_bias[i] = g_bias1[n0 + i];

    float acc[4][4][4];
#pragma unroll
    for (int mf = 0; mf < 4; mf++)
#pragma unroll
        for (int nf = 0; nf < 4; nf++)
#pragma unroll
            for (int e = 0; e < 4; e++) acc[mf][nf][e] = 0.f;

    unsigned aoff = (unsigned)((64 * wm + (lane & 15)) * PJ_ROWB + ((lane & 16) ? 16 : 0));
    int rl = lane & 15;
    unsigned boff = (unsigned)((32 * wn + (rl & 7)) * PJ_ROWB + ((rl & 8) ? 16 : 0));

    pj_load_chunk(sb0,            bt0, n0, 0,     tid); CP_COMMIT();
    pj_load_chunk(sb0 + PJ_STAGE, bt0, n0, PJ_KC, tid); CP_COMMIT();

    for (int c = 0; c < PJ_NCHUNK; c++) {
        unsigned sb = sb0 + (c & 1) * PJ_STAGE;
        if (c < PJ_NCHUNK - 1) { CP_WAIT1(); } else { CP_WAIT0(); }
        __syncthreads();

#pragma unroll
        for (int ks = 0; ks < 2; ks++) {
            unsigned kb = (unsigned)(ks * 32);
            unsigned Ah[4][4], Al[4][4], Bh[4][2], Bl[4][2];
#pragma unroll
            for (int mf = 0; mf < 4; mf++) {
                unsigned ra = sb + aoff + kb + (unsigned)(16 * mf * PJ_ROWB);
                ldm_x4(Ah[mf], ra);
                ldm_x4(Al[mf], ra + PJ_MAT);
            }
#pragma unroll
            for (int nf = 0; nf < 4; nf++) {
                unsigned rb = sb + 2 * PJ_MAT + boff + kb + (unsigned)(8 * nf * PJ_ROWB);
                ldm_x2(Bh[nf], rb);
                ldm_x2(Bl[nf], rb + PJ_MAT);
            }
#pragma unroll
            for (int mf = 0; mf < 4; mf++)
#pragma unroll
                for (int nf = 0; nf < 4; nf++) {
                    mma16816(acc[mf][nf], Ah[mf], Bh[nf]);
                    mma16816(acc[mf][nf], Ah[mf], Bl[nf]);
                    mma16816(acc[mf][nf], Al[mf], Bh[nf]);
                }
        }

        __syncthreads();
        if (c + 2 < PJ_NCHUNK) {
            pj_load_chunk(sb, bt0, n0, (c + 2) * PJ_KC, tid);
            CP_COMMIT();
        }
    }

    int mrow = bt0 + 64 * wm + (lane >> 2);
    int ncol = 32 * wn + 2 * (lane & 3);
#pragma unroll
    for (int mf = 0; mf < 4; mf++) {
#pragma unroll
        for (int nf = 0; nf < 4; nf++) {
            int cc = ncol + 8 * nf;
            float b0 = s_bias[cc], b1 = s_bias[cc + 1];
            float* p0 = &g_xg[(size_t)(mrow + 16 * mf) * Gv + n0 + cc];
            float* p1 = &g_xg[(size_t)(mrow + 16 * mf + 8) * Gv + n0 + cc];
            *(float2*)p0 = make_float2(acc[mf][nf][0] + b0, acc[mf][nf][1] + b1);
            *(float2*)p1 = make_float2(acc[mf][nf][2] + b0, acc[mf][nf][3] + b1);
        }
    }
}

// ---------------------------------------------------------------------------
// Persistent recurrence via HMMA. 128 CTAs x 256 threads.
// CTA: 32 gate cols (= 8 j), weight-stationary bf16 hi/lo in SMEM (129 KB).
// Per step: M=64 batches x N=32, K=1024 in 16x64 chunks (cp.async 2-stage).
// 8 warps = 2m x 4n; same ldmatrix/mma patterns as proj1.
// SMEM map (bytes from base):
//   0      sWh [32][1032 bf16]  (pitch 2064)
//   66048  sWl [32][1032 bf16]
//   132096 sA stage0 hi [64][72 bf16] (pitch 144)
//   141312 sA stage0 lo
//   150528 sA stage1 hi
//   159744 sA stage1 lo
//   168960 sD float [64][36]
// total 178176
// ---------------------------------------------------------------------------
#define LW_PITCHB 2064
#define LA_PITCHB 144
#define LA_MATB   9216        // 64*144
#define LA_STAGEB 18432       // hi+lo
#define LS_SMEM   178176

__device__ __forceinline__ void la_load(unsigned dst,
                                        const __nv_bfloat16* hH,
                                        const __nv_bfloat16* hL,
                                        size_t hstr, int k0, int tid)
{
#pragma unroll
    for (int i = 0; i < 4; i++) {
        int u = tid + 256 * i;         // 0..1023
        int mat = u >> 9;              // 0 hi, 1 lo
        int rr  = (u >> 3) & 63;
        int cc  = u & 7;
        const __nv_bfloat16* s = (mat ? hL : hH) + (size_t)rr * hstr + k0 + cc * 8;
        cp16(dst + mat * LA_MATB + rr * LA_PITCHB + cc * 16, s);
    }
}

__global__ void __launch_bounds__(256, 1)
lstm_mma_kernel(int layer, const float* __restrict__ c0l)
{
    extern __shared__ char sm[];
    unsigned sb = smem_u32(sm);

    const __nv_bfloat16* __restrict__ Wbh = layer ? g_Whh1bh : g_Whh0bh;
    const __nv_bfloat16* __restrict__ Wbl = layer ? g_Whh1bl : g_Whh0bl;
    __nv_bfloat16* __restrict__ seqh = layer ? g_h2bh : g_h1bh;
    __nv_bfloat16* __restrict__ seql = layer ? g_h2bl : g_h1bl;

    int tid  = threadIdx.x;
    int lane = tid & 31;
    int w    = tid >> 5;
    int n0   = blockIdx.x * 32;    // global gate col base
    int j0   = blockIdx.x * 8;     // global hidden unit base

    // one-time W load (hi/lo), 32 rows x 1024 bf16, pitch 1032 bf16
    {
        const unsigned* srcH = (const unsigned*)(Wbh + (size_t)n0 * Hv);
        const unsigned* srcL = (const unsigned*)(Wbl + (size_t)n0 * Hv);
        unsigned* dH = (unsigned*)sm;
        unsigned* dL = (unsigned*)(sm + 66048);
        for (int i = tid; i < 32 * 512; i += 256) {
            int r = i >> 9, cc = i & 511;
            dH[r * 516 + cc] = srcH[r * 512 + cc];
            dL[r * 516 + cc] = srcL[r * 512 + cc];
        }
    }
    __syncthreads();

    // cell state: thread owns cells (b = tid>>3 + 32e, jl = tid&7)
    int ejl = tid & 7;
    int eb  = tid >> 3;
    float c_[2];
    c_[0] = c0l[(size_t)eb * Hv + j0 + ejl];
    c_[1] = c0l[(size_t)(eb + 32) * Hv + j0 + ejl];

    int wm = w & 1, wn = w >> 1;
    unsigned aoff = (unsigned)((32 * wm + (lane & 15)) * LA_PITCHB + ((lane & 16) ? 16 : 0));
    int rl = lane & 15;
    unsigned boffH = sb + (unsigned)((8 * wn + (rl & 7)) * LW_PITCHB + ((rl & 8) ? 16 : 0));
    unsigned boffL = boffH + 66048;
    unsigned sAb = sb + 132096;
    float* sD = (float*)(sm + 168960);

    unsigned lg = g_bar_gen;

    for (int t = 0; t < Tv; t++) {
        const __nv_bfloat16 *hH, *hL;
        size_t hstr;
        if (t == 0) {
            hH = g_h0sh + layer * (Bv * Hv);
            hL = g_h0sl + layer * (Bv * Hv);
            hstr = Hv;
        } else {
            hH = seqh + (size_t)(t - 1) * Hv;
            hL = seql + (size_t)(t - 1) * Hv;
            hstr = (size_t)Tv * Hv;
        }

        float acc[2][4];
#pragma unroll
        for (int mf = 0; mf < 2; mf++)
#pragma unroll
            for (int e = 0; e < 4; e++) acc[mf][e] = 0.f;

        la_load(sAb,             hH, hL, hstr, 0,  tid); CP_COMMIT();
        la_load(sAb + LA_STAGEB, hH, hL, hstr, 64, tid); CP_COMMIT();

        for (int ch = 0; ch < 16; ch++) {
            unsigned ab = sAb + (ch & 1) * LA_STAGEB;
            if (ch < 15) { CP_WAIT1(); } else { CP_WAIT0(); }
            __syncthreads();

#pragma unroll
            for (int ks = 0; ks < 4; ks++) {
                unsigned kb = (unsigned)(ks * 32);             // A byte offset
                unsigned wkb = (unsigned)((ch * 64 + ks * 16) * 2); // W byte offset
                unsigned Ah[2][4], Al[2][4], Bh[2], Bl[2];
#pragma unroll
                for (int mf = 0; mf < 2; mf++) {
                    unsigned ra = ab + aoff + kb + (unsigned)(16 * mf * LA_PITCHB);
                    ldm_x4(Ah[mf], ra);
                    ldm_x4(Al[mf], ra + LA_MATB);
                }
                ldm_x2(Bh, boffH + wkb);
                ldm_x2(Bl, boffL + wkb);
#pragma unroll
                for (int mf = 0; mf < 2; mf++) {
                    mma16816(acc[mf], Ah[mf], Bh);
                    mma16816(acc[mf], Ah[mf], Bl);
                    mma16816(acc[mf], Al[mf], Bh);
                }
            }

            __syncthreads();
            if (ch + 2 < 16) {
                la_load(ab, hH, hL, hstr, (ch + 2) * 64, tid);
                CP_COMMIT();
            }
        }

        // stage D frags to smem
        {
            int mrow = 32 * wm + (lane >> 2);
            int col  = 8 * wn + 2 * (lane & 3);
#pragma unroll
            for (int mf = 0; mf < 2; mf++) {
                *(float2*)&sD[(mrow + 16 * mf) * 36 + col]     = make_float2(acc[mf][0], acc[mf][1]);
                *(float2*)&sD[(mrow + 16 * mf + 8) * 36 + col] = make_float2(acc[mf][2], acc[mf][3]);
            }
        }
        __syncthreads();

        // epilogue: 2 cells per thread
#pragma unroll
        for (int e = 0; e < 2; e++) {
            int b = eb + 32 * e;
            float4 d  = *(const float4*)&sD[b * 36 + 4 * ejl];
            float4 xg = *(const float4*)&g_xg[((size_t)b * Tv + t) * Gv + n0 + 4 * ejl];
            float i_ = sigf(d.x + xg.x);
            float f_ = sigf(d.y + xg.y);
            float gg = tanhf(d.z + xg.z);
            float o_ = sigf(d.w + xg.w);
            float c = f_ * c_[e] + i_ * gg;
            c_[e] = c;
            float h = o_ * tanhf(c);
            __nv_bfloat16 hi = __float2bfloat16(h);
            size_t idx = ((size_t)b * Tv + t) * Hv + j0 + ejl;
            seqh[idx] = hi;
            seql[idx] = __float2bfloat16(h - __bfloat162float(hi));
            if (layer) g_h2[idx] = h;
        }

        if (t != Tv - 1) grid_barrier(lg);
    }
}

// ---------------------------------------------------------------------------
// Final FC
// ---------------------------------------------------------------------------
__global__ void fc_kernel(const float* __restrict__ Wfc, const float* __restrict__ bfc,
                          float* __restrict__ out)
{
    int bt = blockIdx.x * 8 + (threadIdx.x >> 5);
    int lane = threadIdx.x & 31;
    const float* hrow = g_h2 + (size_t)bt * Hv;
    float s = 0.f;
#pragma unroll 8
    for (int k = lane; k < Hv; k += 32) s += hrow[k] * Wfc[k];
#pragma unroll
    for (int off = 16; off; off >>= 1) s += __shfl_down_sync(0xFFFFFFFFu, s, off);
    if (lane == 0) out[bt] = s + bfc[0];
}

// ---------------------------------------------------------------------------
// Launch (6 graph nodes)
// ---------------------------------------------------------------------------
extern "C" void kernel_launch(void* const* d_in, const int* in_sizes, int n_in,
                              void* d_out, int out_size)
{
    (void)in_sizes; (void)n_in; (void)out_size;
    const float* x    = (const float*)d_in[0];
    const float* h0   = (const float*)d_in[1];
    const float* c0   = (const float*)d_in[2];
    const float* Wih0 = (const float*)d_in[3];
    const float* Whh0 = (const float*)d_in[4];
    const float* bih0 = (const float*)d_in[5];
    const float* bhh0 = (const float*)d_in[6];
    const float* Wih1 = (const float*)d_in[7];
    const float* Whh1 = (const float*)d_in[8];
    const float* bih1 = (const float*)d_in[9];
    const float* bhh1 = (const float*)d_in[10];
    const float* Wfc  = (const float*)d_in[11];
    const float* bfc  = (const float*)d_in[12];
    float* out = (float*)d_out;

    cudaFuncSetAttribute(lstm_mma_kernel,
                         cudaFuncAttributeMaxDynamicSharedMemorySize, LS_SMEM);
    cudaFuncSetAttribute(proj1_mma_kernel,
                         cudaFuncAttributeMaxDynamicSharedMemorySize, PJ_SMEM);

    prep_kernel<<<2048, 256>>>(Whh0, Whh1, Wih0, Wih1, bih0, bhh0, bih1, bhh1, h0);

    // Layer 0
    proj0_kernel<<<dim3(Gv / 128, BTv / 64), 256>>>(x);
    lstm_mma_kernel<<<NBLK, 256, LS_SMEM>>>(0, c0);

    // Layer 1
    proj1_mma_kernel<<<dim3(Gv / 128, BTv / 128), 256, PJ_SMEM>>>();
    lstm_mma_kernel<<<NBLK, 256, LS_SMEM>>>(1, c0 + (size_t)Bv * Hv);

    fc_kernel<<<BTv / 8, 256>>>(Wfc, bfc, out);
}

// round 8
// speedup vs baseline: 3.6916x; 1.0826x over previous
#include <cuda_runtime.h>
#include <cuda_bf16.h>
#include <math.h>

// Problem dims
#define Bv 64
#define Tv 512
#define Iv 128
#define Hv 1024
#define Gv 4096          // 4*H
#define BTv (Bv*Tv)      // 32768

#define NBLK 128         // persistent CTAs for recurrence

// ---------------------------------------------------------------------------
// Static device scratch
// ---------------------------------------------------------------------------
__device__ float g_xg[(size_t)BTv * Gv];       // [B,T,4H] gate pre-activations
__device__ float g_h2[(size_t)BTv * Hv];       // layer-1 output fp32 (for fc)
__device__ float g_WihT0[Iv * Gv];
__device__ float g_bias0[Gv];
__device__ float g_bias1[Gv];

// bf16 hi/lo h sequences (written by recurrence epilogues)
__device__ __nv_bfloat16 g_h1bh[(size_t)BTv * Hv];
__device__ __nv_bfloat16 g_h1bl[(size_t)BTv * Hv];
__device__ __nv_bfloat16 g_h2bh[(size_t)BTv * Hv];
__device__ __nv_bfloat16 g_h2bl[(size_t)BTv * Hv];

// bf16 hi/lo weights, [c = 4j+q][k] layout
__device__ __nv_bfloat16 g_Wbh[(size_t)Gv * Hv];     // W_ih1 (proj1 B)
__device__ __nv_bfloat16 g_Wbl[(size_t)Gv * Hv];
__device__ __nv_bfloat16 g_Whh0bh[(size_t)Gv * Hv];  // W_hh0
__device__ __nv_bfloat16 g_Whh0bl[(size_t)Gv * Hv];
__device__ __nv_bfloat16 g_Whh1bh[(size_t)Gv * Hv];  // W_hh1
__device__ __nv_bfloat16 g_Whh1bl[(size_t)Gv * Hv];

// h0 bf16 hi/lo split: [2][64][1024]
__device__ __nv_bfloat16 g_h0sh[2 * Bv * Hv];
__device__ __nv_bfloat16 g_h0sl[2 * Bv * Hv];

// software grid barrier
__device__ unsigned g_bar_count = 0;
__device__ volatile unsigned g_bar_gen = 0;

__device__ __forceinline__ void grid_barrier(unsigned& local_gen)
{
    __threadfence();
    __syncthreads();
    if (threadIdx.x == 0) {
        unsigned gen = local_gen;
        if (atomicAdd(&g_bar_count, 1u) == NBLK - 1) {
            g_bar_count = 0;
            __threadfence();
            g_bar_gen = gen + 1;
        } else {
            while (g_bar_gen == gen) { }
        }
        __threadfence();
    }
    __syncthreads();
    local_gen++;
}

// ---------------------------------------------------------------------------
// f32x2 packed helpers (proj0)
// ---------------------------------------------------------------------------
__device__ __forceinline__ void ffma2(unsigned long long& d,
                                      unsigned long long a, unsigned long long b)
{
    asm("fma.rn.f32x2 %0, %1, %2, %0;" : "+l"(d) : "l"(a), "l"(b));
}
__device__ __forceinline__ unsigned long long f2dup(float x)
{
    unsigned long long r;
    asm("mov.b64 %0, {%1, %1};" : "=l"(r) : "f"(x));
    return r;
}
__device__ __forceinline__ float2 f2unpk(unsigned long long v)
{
    float2 r;
    asm("mov.b64 {%0, %1}, %2;" : "=f"(r.x), "=f"(r.y) : "l"(v));
    return r;
}

// ---------------------------------------------------------------------------
// HMMA / ldmatrix / cp.async helpers
// ---------------------------------------------------------------------------
__device__ __forceinline__ unsigned smem_u32(const void* p)
{
    unsigned a;
    asm("{ .reg .u64 t; cvta.to.shared.u64 t, %1; cvt.u32.u64 %0, t; }"
        : "=r"(a) : "l"(p));
    return a;
}
__device__ __forceinline__ void ldm_x4(unsigned r[4], unsigned addr)
{
    asm volatile("ldmatrix.sync.aligned.m8n8.x4.shared.b16 {%0,%1,%2,%3}, [%4];"
                 : "=r"(r[0]), "=r"(r[1]), "=r"(r[2]), "=r"(r[3]) : "r"(addr));
}
__device__ __forceinline__ void ldm_x2(unsigned r[2], unsigned addr)
{
    asm volatile("ldmatrix.sync.aligned.m8n8.x2.shared.b16 {%0,%1}, [%2];"
                 : "=r"(r[0]), "=r"(r[1]) : "r"(addr));
}
__device__ __forceinline__ void mma16816(float d[4], const unsigned a[4], const unsigned b[2])
{
    asm volatile("mma.sync.aligned.m16n8k16.row.col.f32.bf16.bf16.f32 "
                 "{%0,%1,%2,%3}, {%4,%5,%6,%7}, {%8,%9}, {%0,%1,%2,%3};"
                 : "+f"(d[0]), "+f"(d[1]), "+f"(d[2]), "+f"(d[3])
                 : "r"(a[0]), "r"(a[1]), "r"(a[2]), "r"(a[3]), "r"(b[0]), "r"(b[1]));
}
__device__ __forceinline__ void cp16(unsigned dst, const void* src)
{
    asm volatile("cp.async.cg.shared.global [%0], [%1], 16;"
                 :: "r"(dst), "l"(src) : "memory");
}
#define CP_COMMIT() asm volatile("cp.async.commit_group;" ::: "memory")
#define CP_WAIT2()  asm volatile("cp.async.wait_group 2;" ::: "memory")
#define CP_WAIT1()  asm volatile("cp.async.wait_group 1;" ::: "memory")
#define CP_WAIT0()  asm volatile("cp.async.wait_group 0;" ::: "memory")

__device__ __forceinline__ float sigf(float v) { return 1.0f / (1.0f + expf(-v)); }

// ---------------------------------------------------------------------------
// Prep: all weight transforms + h0 split.
// ---------------------------------------------------------------------------
__global__ void prep_kernel(const float* __restrict__ Whh0, const float* __restrict__ Whh1,
                            const float* __restrict__ Wih0, const float* __restrict__ Wih1,
                            const float* __restrict__ bih0, const float* __restrict__ bhh0,
                            const float* __restrict__ bih1, const float* __restrict__ bhh1,
                            const float* __restrict__ h0)
{
    size_t stride = (size_t)gridDim.x * blockDim.x;
    size_t tid0 = (size_t)blockIdx.x * blockDim.x + threadIdx.x;

    for (size_t s = tid0; s < (size_t)Gv * Hv; s += stride) {
        int row = (int)(s >> 10);
        int k   = (int)(s & 1023);
        int q = row >> 10;
        int j = row & 1023;
        size_t bdst = (size_t)(4 * j + q) * Hv + k;

        float v = Whh0[s];
        __nv_bfloat16 hi = __float2bfloat16(v);
        g_Whh0bh[bdst] = hi;
        g_Whh0bl[bdst] = __float2bfloat16(v - __bfloat162float(hi));

        v = Whh1[s];
        hi = __float2bfloat16(v);
        g_Whh1bh[bdst] = hi;
        g_Whh1bl[bdst] = __float2bfloat16(v - __bfloat162float(hi));

        v = Wih1[s];
        hi = __float2bfloat16(v);
        g_Wbh[bdst] = hi;
        g_Wbl[bdst] = __float2bfloat16(v - __bfloat162float(hi));
    }
    for (size_t s = tid0; s < (size_t)Gv * Iv; s += stride) {
        int row = (int)(s >> 7);
        int k   = (int)(s & 127);
        int q = row >> 10;
        int j = row & 1023;
        g_WihT0[(size_t)k * Gv + 4 * j + q] = Wih0[s];
    }
    for (size_t s = tid0; s < (size_t)Gv; s += stride) {
        int q = (int)(s >> 10);
        int j = (int)(s & 1023);
        g_bias0[4 * j + q] = bih0[s] + bhh0[s];
        g_bias1[4 * j + q] = bih1[s] + bhh1[s];
    }
    for (size_t s = tid0; s < (size_t)2 * Bv * Hv; s += stride) {
        float v = h0[s];
        __nv_bfloat16 hi = __float2bfloat16(v);
        g_h0sh[s] = hi;
        g_h0sl[s] = __float2bfloat16(v - __bfloat162float(hi));
    }
}

// ---------------------------------------------------------------------------
// proj0: x[32768,128] @ WihT0 -> g_xg (FFMA path, small)
// ---------------------------------------------------------------------------
__global__ void proj0_kernel(const float* __restrict__ A)
{
    const float* __restrict__ WT   = g_WihT0;
    const float* __restrict__ bias = g_bias0;

    __shared__ float sA[64][17];

    int g0  = blockIdx.x * 128;
    int bt0 = blockIdx.y * 64;
    int tx = threadIdx.x & 31;
    int ty = threadIdx.x >> 5;

    unsigned long long a01[8], a23[8];
#pragma unroll
    for (int r = 0; r < 8; r++) { a01[r] = 0ull; a23[r] = 0ull; }

    const float* wp = WT + (size_t)g0 + 4 * tx;

    for (int k0 = 0; k0 < Iv; k0 += 16) {
        __syncthreads();
#pragma unroll
        for (int e = 0; e < 4; e++) {
            int lin = threadIdx.x + 256 * e;
            int r  = lin >> 4;
            int kk = lin & 15;
            sA[r][kk] = A[(size_t)(bt0 + r) * Iv + k0 + kk];
        }
        __syncthreads();
#pragma unroll
        for (int kk = 0; kk < 16; kk++) {
            ulonglong2 w = *(const ulonglong2*)(wp + (size_t)(k0 + kk) * Gv);
#pragma unroll
            for (int r = 0; r < 8; r++) {
                unsigned long long da = f2dup(sA[ty * 8 + r][kk]);
                ffma2(a01[r], w.x, da);
                ffma2(a23[r], w.y, da);
            }
        }
    }

    float4 bv = *(const float4*)&bias[g0 + 4 * tx];
#pragma unroll
    for (int r = 0; r < 8; r++) {
        float2 p01 = f2unpk(a01[r]);
        float2 p23 = f2unpk(a23[r]);
        float4 o;
        o.x = p01.x + bv.x;
        o.y = p01.y + bv.y;
        o.z = p23.x + bv.z;
        o.w = p23.y + bv.w;
        *(float4*)&g_xg[(size_t)(bt0 + ty * 8 + r) * Gv + g0 + 4 * tx] = o;
    }
}

// ---------------------------------------------------------------------------
// proj1 via HMMA — now 2 CTAs/SM for tensor-pipe utilization.
// ---------------------------------------------------------------------------
#define PJ_KC 32
#define PJ_NCHUNK (Hv / PJ_KC)
#define PJ_ROWB 80
#define PJ_MAT  (128 * PJ_ROWB)
#define PJ_STAGE (4 * PJ_MAT)
#define PJ_SMEM  (2 * PJ_STAGE)

__device__ __forceinline__ void pj_load_chunk(unsigned sbase, int bt0, int n0, int k0, int tid)
{
#pragma unroll
    for (int i = 0; i < 8; i++) {
        int u = tid + 256 * i;
        int mat = u >> 9;
        int rr  = (u >> 2) & 127;
        int cc  = u & 3;
        unsigned dst = sbase + mat * PJ_MAT + rr * PJ_ROWB + cc * 16;
        const __nv_bfloat16* src;
        if      (mat == 0) src = g_h1bh + (size_t)(bt0 + rr) * Hv + k0 + cc * 8;
        else if (mat == 1) src = g_h1bl + (size_t)(bt0 + rr) * Hv + k0 + cc * 8;
        else if (mat == 2) src = g_Wbh  + (size_t)(n0  + rr) * Hv + k0 + cc * 8;
        else               src = g_Wbl  + (size_t)(n0  + rr) * Hv + k0 + cc * 8;
        cp16(dst, src);
    }
}

__global__ void __launch_bounds__(256, 2)
proj1_mma_kernel()
{
    extern __shared__ char dsm[];
    unsigned sb0 = smem_u32(dsm);

    __shared__ float s_bias[128];

    int tid  = threadIdx.x;
    int lane = tid & 31;
    int w    = tid >> 5;
    int wm   = w & 1;
    int wn   = w >> 1;
    int n0   = blockIdx.x * 128;
    int bt0  = blockIdx.y * 128;

    for (int i = tid; i < 128; i += 256) s_bias[i] = g_bias1[n0 + i];

    float acc[4][4][4];
#pragma unroll
    for (int mf = 0; mf < 4; mf++)
#pragma unroll
        for (int nf = 0; nf < 4; nf++)
#pragma unroll
            for (int e = 0; e < 4; e++) acc[mf][nf][e] = 0.f;

    unsigned aoff = (unsigned)((64 * wm + (lane & 15)) * PJ_ROWB + ((lane & 16) ? 16 : 0));
    int rl = lane & 15;
    unsigned boff = (unsigned)((32 * wn + (rl & 7)) * PJ_ROWB + ((rl & 8) ? 16 : 0));

    pj_load_chunk(sb0,            bt0, n0, 0,     tid); CP_COMMIT();
    pj_load_chunk(sb0 + PJ_STAGE, bt0, n0, PJ_KC, tid); CP_COMMIT();

    for (int c = 0; c < PJ_NCHUNK; c++) {
        unsigned sb = sb0 + (c & 1) * PJ_STAGE;
        if (c < PJ_NCHUNK - 1) { CP_WAIT1(); } else { CP_WAIT0(); }
        __syncthreads();

#pragma unroll
        for (int ks = 0; ks < 2; ks++) {
            unsigned kb = (unsigned)(ks * 32);
            unsigned Ah[4][4], Al[4][4], Bh[4][2], Bl[4][2];
#pragma unroll
            for (int mf = 0; mf < 4; mf++) {
                unsigned ra = sb + aoff + kb + (unsigned)(16 * mf * PJ_ROWB);
                ldm_x4(Ah[mf], ra);
                ldm_x4(Al[mf], ra + PJ_MAT);
            }
#pragma unroll
            for (int nf = 0; nf < 4; nf++) {
                unsigned rb = sb + 2 * PJ_MAT + boff + kb + (unsigned)(8 * nf * PJ_ROWB);
                ldm_x2(Bh[nf], rb);
                ldm_x2(Bl[nf], rb + PJ_MAT);
            }
#pragma unroll
            for (int mf = 0; mf < 4; mf++)
#pragma unroll
                for (int nf = 0; nf < 4; nf++) {
                    mma16816(acc[mf][nf], Ah[mf], Bh[nf]);
                    mma16816(acc[mf][nf], Ah[mf], Bl[nf]);
                    mma16816(acc[mf][nf], Al[mf], Bh[nf]);
                }
        }

        __syncthreads();
        if (c + 2 < PJ_NCHUNK) {
            pj_load_chunk(sb, bt0, n0, (c + 2) * PJ_KC, tid);
            CP_COMMIT();
        }
    }

    int mrow = bt0 + 64 * wm + (lane >> 2);
    int ncol = 32 * wn + 2 * (lane & 3);
#pragma unroll
    for (int mf = 0; mf < 4; mf++) {
#pragma unroll
        for (int nf = 0; nf < 4; nf++) {
            int cc = ncol + 8 * nf;
            float b0 = s_bias[cc], b1 = s_bias[cc + 1];
            float* p0 = &g_xg[(size_t)(mrow + 16 * mf) * Gv + n0 + cc];
            float* p1 = &g_xg[(size_t)(mrow + 16 * mf + 8) * Gv + n0 + cc];
            *(float2*)p0 = make_float2(acc[mf][nf][0] + b0, acc[mf][nf][1] + b1);
            *(float2*)p1 = make_float2(acc[mf][nf][2] + b0, acc[mf][nf][3] + b1);
        }
    }
}

// ---------------------------------------------------------------------------
// Persistent recurrence via HMMA, 4-stage cp.async pipeline.
// 128 CTAs x 256 threads. CTA: 32 gate cols (8 j), W stationary bf16 hi/lo.
// Per step: M=64 x N=32, K=1024 in 16x64 chunks, 4 stages, 1 sync/chunk.
// SMEM map (bytes):
//   0       sWh [32][1032 bf16] (pitch 2064)
//   66048   sWl
//   132096  sA stages 0..3, each hi[64][72]+lo (18432 B)
//   205824  sD float [64][36]  (9216 B)
// total 215040
// ---------------------------------------------------------------------------
#define LW_PITCHB 2064
#define LA_PITCHB 144
#define LA_MATB   9216
#define LA_STAGEB 18432
#define LS_SMEM   215040

__device__ __forceinline__ void la_load(unsigned dst,
                                        const __nv_bfloat16* hH,
                                        const __nv_bfloat16* hL,
                                        size_t hstr, int k0, int tid)
{
#pragma unroll
    for (int i = 0; i < 4; i++) {
        int u = tid + 256 * i;
        int mat = u >> 9;
        int rr  = (u >> 3) & 63;
        int cc  = u & 7;
        const __nv_bfloat16* s = (mat ? hL : hH) + (size_t)rr * hstr + k0 + cc * 8;
        cp16(dst + mat * LA_MATB + rr * LA_PITCHB + cc * 16, s);
    }
}

__global__ void __launch_bounds__(256, 1)
lstm_mma_kernel(int layer, const float* __restrict__ c0l)
{
    extern __shared__ char sm[];
    unsigned sb = smem_u32(sm);

    const __nv_bfloat16* __restrict__ Wbh = layer ? g_Whh1bh : g_Whh0bh;
    const __nv_bfloat16* __restrict__ Wbl = layer ? g_Whh1bl : g_Whh0bl;
    __nv_bfloat16* __restrict__ seqh = layer ? g_h2bh : g_h1bh;
    __nv_bfloat16* __restrict__ seql = layer ? g_h2bl : g_h1bl;

    int tid  = threadIdx.x;
    int lane = tid & 31;
    int w    = tid >> 5;
    int n0   = blockIdx.x * 32;
    int j0   = blockIdx.x * 8;

    // one-time W load (hi/lo)
    {
        const unsigned* srcH = (const unsigned*)(Wbh + (size_t)n0 * Hv);
        const unsigned* srcL = (const unsigned*)(Wbl + (size_t)n0 * Hv);
        unsigned* dH = (unsigned*)sm;
        unsigned* dL = (unsigned*)(sm + 66048);
        for (int i = tid; i < 32 * 512; i += 256) {
            int r = i >> 9, cc = i & 511;
            dH[r * 516 + cc] = srcH[r * 512 + cc];
            dL[r * 516 + cc] = srcL[r * 512 + cc];
        }
    }
    __syncthreads();

    int ejl = tid & 7;
    int eb  = tid >> 3;
    float c_[2];
    c_[0] = c0l[(size_t)eb * Hv + j0 + ejl];
    c_[1] = c0l[(size_t)(eb + 32) * Hv + j0 + ejl];

    int wm = w & 1, wn = w >> 1;
    unsigned aoff = (unsigned)((32 * wm + (lane & 15)) * LA_PITCHB + ((lane & 16) ? 16 : 0));
    int rl = lane & 15;
    unsigned boffH = sb + (unsigned)((8 * wn + (rl & 7)) * LW_PITCHB + ((rl & 8) ? 16 : 0));
    unsigned boffL = boffH + 66048;
    unsigned sAb = sb + 132096;
    float* sD = (float*)(sm + 205824);

    unsigned lg = g_bar_gen;

    for (int t = 0; t < Tv; t++) {
        const __nv_bfloat16 *hH, *hL;
        size_t hstr;
        if (t == 0) {
            hH = g_h0sh + layer * (Bv * Hv);
            hL = g_h0sl + layer * (Bv * Hv);
            hstr = Hv;
        } else {
            hH = seqh + (size_t)(t - 1) * Hv;
            hL = seql + (size_t)(t - 1) * Hv;
            hstr = (size_t)Tv * Hv;
        }

        // prologue: 3 chunks in flight
        la_load(sAb,                 hH, hL, hstr, 0,   tid); CP_COMMIT();
        la_load(sAb + LA_STAGEB,     hH, hL, hstr, 64,  tid); CP_COMMIT();
        la_load(sAb + 2 * LA_STAGEB, hH, hL, hstr, 128, tid); CP_COMMIT();

        // prefetch xg (L2) while chunks stream
        float4 xg0 = *(const float4*)&g_xg[((size_t)eb * Tv + t) * Gv + n0 + 4 * ejl];
        float4 xg1 = *(const float4*)&g_xg[((size_t)(eb + 32) * Tv + t) * Gv + n0 + 4 * ejl];

        float acc[2][4];
#pragma unroll
        for (int mf = 0; mf < 2; mf++)
#pragma unroll
            for (int e = 0; e < 4; e++) acc[mf][e] = 0.f;

        for (int ch = 0; ch < 16; ch++) {
            unsigned ab = sAb + (ch & 3) * LA_STAGEB;
            if (ch <= 13)      { CP_WAIT2(); }
            else if (ch == 14) { CP_WAIT1(); }
            else               { CP_WAIT0(); }
            __syncthreads();

            // issue next load first (overlaps with compute below)
            if (ch + 3 < 16) {
                la_load(sAb + ((ch + 3) & 3) * LA_STAGEB, hH, hL, hstr, (ch + 3) * 64, tid);
                CP_COMMIT();
            }

#pragma unroll
            for (int ks = 0; ks < 4; ks++) {
                unsigned kb = (unsigned)(ks * 32);
                unsigned wkb = (unsigned)((ch * 64 + ks * 16) * 2);
                unsigned Ah[2][4], Al[2][4], Bh[2], Bl[2];
#pragma unroll
                for (int mf = 0; mf < 2; mf++) {
                    unsigned ra = ab + aoff + kb + (unsigned)(16 * mf * LA_PITCHB);
                    ldm_x4(Ah[mf], ra);
                    ldm_x4(Al[mf], ra + LA_MATB);
                }
                ldm_x2(Bh, boffH + wkb);
                ldm_x2(Bl, boffL + wkb);
#pragma unroll
                for (int mf = 0; mf < 2; mf++) {
                    mma16816(acc[mf], Ah[mf], Bh);
                    mma16816(acc[mf], Ah[mf], Bl);
                    mma16816(acc[mf], Al[mf], Bh);
                }
            }
        }

        // stage D frags to smem
        {
            int mrow = 32 * wm + (lane >> 2);
            int col  = 8 * wn + 2 * (lane & 3);
#pragma unroll
            for (int mf = 0; mf < 2; mf++) {
                *(float2*)&sD[(mrow + 16 * mf) * 36 + col]     = make_float2(acc[mf][0], acc[mf][1]);
                *(float2*)&sD[(mrow + 16 * mf + 8) * 36 + col] = make_float2(acc[mf][2], acc[mf][3]);
            }
        }
        __syncthreads();

        // epilogue: 2 cells per thread
#pragma unroll
        for (int e = 0; e < 2; e++) {
            int b = eb + 32 * e;
            float4 d  = *(const float4*)&sD[b * 36 + 4 * ejl];
            float4 xg = e ? xg1 : xg0;
            float i_ = sigf(d.x + xg.x);
            float f_ = sigf(d.y + xg.y);
            float gg = tanhf(d.z + xg.z);
            float o_ = sigf(d.w + xg.w);
            float c = f_ * c_[e] + i_ * gg;
            c_[e] = c;
            float h = o_ * tanhf(c);
            __nv_bfloat16 hi = __float2bfloat16(h);
            size_t idx = ((size_t)b * Tv + t) * Hv + j0 + ejl;
            seqh[idx] = hi;
            seql[idx] = __float2bfloat16(h - __bfloat162float(hi));
            if (layer) g_h2[idx] = h;
        }

        if (t != Tv - 1) grid_barrier(lg);
    }
}

// ---------------------------------------------------------------------------
// Final FC
// ---------------------------------------------------------------------------
__global__ void fc_kernel(const float* __restrict__ Wfc, const float* __restrict__ bfc,
                          float* __restrict__ out)
{
    int bt = blockIdx.x * 8 + (threadIdx.x >> 5);
    int lane = threadIdx.x & 31;
    const float* hrow = g_h2 + (size_t)bt * Hv;
    float s = 0.f;
#pragma unroll 8
    for (int k = lane; k < Hv; k += 32) s += hrow[k] * Wfc[k];
#pragma unroll
    for (int off = 16; off; off >>= 1) s += __shfl_down_sync(0xFFFFFFFFu, s, off);
    if (lane == 0) out[bt] = s + bfc[0];
}

// ---------------------------------------------------------------------------
// Launch (6 graph nodes)
// ---------------------------------------------------------------------------
extern "C" void kernel_launch(void* const* d_in, const int* in_sizes, int n_in,
                              void* d_out, int out_size)
{
    (void)in_sizes; (void)n_in; (void)out_size;
    const float* x    = (const float*)d_in[0];
    const float* h0   = (const float*)d_in[1];
    const float* c0   = (const float*)d_in[2];
    const float* Wih0 = (const float*)d_in[3];
    const float* Whh0 = (const float*)d_in[4];
    const float* bih0 = (const float*)d_in[5];
    const float* bhh0 = (const float*)d_in[6];
    const float* Wih1 = (const float*)d_in[7];
    const float* Whh1 = (const float*)d_in[8];
    const float* bih1 = (const float*)d_in[9];
    const float* bhh1 = (const float*)d_in[10];
    const float* Wfc  = (const float*)d_in[11];
    const float* bfc  = (const float*)d_in[12];
    float* out = (float*)d_out;

    cudaFuncSetAttribute(lstm_mma_kernel,
                         cudaFuncAttributeMaxDynamicSharedMemorySize, LS_SMEM);
    cudaFuncSetAttribute(proj1_mma_kernel,
                         cudaFuncAttributeMaxDynamicSharedMemorySize, PJ_SMEM);

    prep_kernel<<<2048, 256>>>(Whh0, Whh1, Wih0, Wih1, bih0, bhh0, bih1, bhh1, h0);

    // Layer 0
    proj0_kernel<<<dim3(Gv / 128, BTv / 64), 256>>>(x);
    lstm_mma_kernel<<<NBLK, 256, LS_SMEM>>>(0, c0);

    // Layer 1
    proj1_mma_kernel<<<dim3(Gv / 128, BTv / 128), 256, PJ_SMEM>>>();
    lstm_mma_kernel<<<NBLK, 256, LS_SMEM>>>(1, c0 + (size_t)Bv * Hv);

    fc_kernel<<<BTv / 8, 256>>>(Wfc, bfc, out);
}

// round 9
// speedup vs baseline: 5.4026x; 1.4635x over previous
#include <cuda_runtime.h>
#include <cuda_fp16.h>
#include <math.h>

// Problem dims
#define Bv 64
#define Tv 512
#define Iv 128
#define Hv 1024
#define Gv 4096          // 4*H
#define BTv (Bv*Tv)      // 32768

#define NBLK 128         // persistent CTAs for recurrence

// ---------------------------------------------------------------------------
// Static device scratch
// ---------------------------------------------------------------------------
__device__ float g_xg[(size_t)BTv * Gv];       // [B,T,4H] gate pre-activations
__device__ float g_h2[(size_t)BTv * Hv];       // layer-1 output fp32 (for fc)
__device__ float g_WihT0[Iv * Gv];
__device__ float g_bias0[Gv];
__device__ float g_bias1[Gv];

// fp16 h sequences (single precision-level; written by recurrence epilogues)
__device__ __half g_h1f[(size_t)BTv * Hv];
__device__ __half g_h2f[(size_t)BTv * Hv];

// fp16 hi/lo weights, [c = 4j+q][k] layout
__device__ __half g_Wfh[(size_t)Gv * Hv];      // W_ih1 (proj1 B) hi
__device__ __half g_Wfl[(size_t)Gv * Hv];      // lo
__device__ __half g_W0h[(size_t)Gv * Hv];      // W_hh0
__device__ __half g_W0l[(size_t)Gv * Hv];
__device__ __half g_W1h[(size_t)Gv * Hv];      // W_hh1
__device__ __half g_W1l[(size_t)Gv * Hv];

// h0 fp16: [2][64][1024]
__device__ __half g_h0s[2 * Bv * Hv];

// software grid barrier
__device__ unsigned g_bar_count = 0;
__device__ volatile unsigned g_bar_gen = 0;

__device__ __forceinline__ void grid_barrier(unsigned& local_gen)
{
    __threadfence();
    __syncthreads();
    if (threadIdx.x == 0) {
        unsigned gen = local_gen;
        if (atomicAdd(&g_bar_count, 1u) == NBLK - 1) {
            g_bar_count = 0;
            __threadfence();
            g_bar_gen = gen + 1;
        } else {
            while (g_bar_gen == gen) { }
        }
        __threadfence();
    }
    __syncthreads();
    local_gen++;
}

// ---------------------------------------------------------------------------
// f32x2 packed helpers (proj0)
// ---------------------------------------------------------------------------
__device__ __forceinline__ void ffma2(unsigned long long& d,
                                      unsigned long long a, unsigned long long b)
{
    asm("fma.rn.f32x2 %0, %1, %2, %0;" : "+l"(d) : "l"(a), "l"(b));
}
__device__ __forceinline__ unsigned long long f2dup(float x)
{
    unsigned long long r;
    asm("mov.b64 %0, {%1, %1};" : "=l"(r) : "f"(x));
    return r;
}
__device__ __forceinline__ float2 f2unpk(unsigned long long v)
{
    float2 r;
    asm("mov.b64 {%0, %1}, %2;" : "=f"(r.x), "=f"(r.y) : "l"(v));
    return r;
}

// ---------------------------------------------------------------------------
// HMMA / ldmatrix / cp.async helpers
// ---------------------------------------------------------------------------
__device__ __forceinline__ unsigned smem_u32(const void* p)
{
    unsigned a;
    asm("{ .reg .u64 t; cvta.to.shared.u64 t, %1; cvt.u32.u64 %0, t; }"
        : "=r"(a) : "l"(p));
    return a;
}
__device__ __forceinline__ void ldm_x4(unsigned r[4], unsigned addr)
{
    asm volatile("ldmatrix.sync.aligned.m8n8.x4.shared.b16 {%0,%1,%2,%3}, [%4];"
                 : "=r"(r[0]), "=r"(r[1]), "=r"(r[2]), "=r"(r[3]) : "r"(addr));
}
__device__ __forceinline__ void ldm_x2(unsigned r[2], unsigned addr)
{
    asm volatile("ldmatrix.sync.aligned.m8n8.x2.shared.b16 {%0,%1}, [%2];"
                 : "=r"(r[0]), "=r"(r[1]) : "r"(addr));
}
__device__ __forceinline__ void mma16816f(float d[4], const unsigned a[4], const unsigned b[2])
{
    asm volatile("mma.sync.aligned.m16n8k16.row.col.f32.f16.f16.f32 "
                 "{%0,%1,%2,%3}, {%4,%5,%6,%7}, {%8,%9}, {%0,%1,%2,%3};"
                 : "+f"(d[0]), "+f"(d[1]), "+f"(d[2]), "+f"(d[3])
                 : "r"(a[0]), "r"(a[1]), "r"(a[2]), "r"(a[3]), "r"(b[0]), "r"(b[1]));
}
__device__ __forceinline__ void cp16(unsigned dst, const void* src)
{
    asm volatile("cp.async.cg.shared.global [%0], [%1], 16;"
                 :: "r"(dst), "l"(src) : "memory");
}
#define CP_COMMIT() asm volatile("cp.async.commit_group;" ::: "memory")
#define CP_WAIT2()  asm volatile("cp.async.wait_group 2;" ::: "memory")
#define CP_WAIT1()  asm volatile("cp.async.wait_group 1;" ::: "memory")
#define CP_WAIT0()  asm volatile("cp.async.wait_group 0;" ::: "memory")

__device__ __forceinline__ float sigf(float v) { return 1.0f / (1.0f + expf(-v)); }

// ---------------------------------------------------------------------------
// Prep: weight transforms (fp16 hi/lo) + proj0 transpose + h0 fp16.
// ---------------------------------------------------------------------------
__global__ void prep_kernel(const float* __restrict__ Whh0, const float* __restrict__ Whh1,
                            const float* __restrict__ Wih0, const float* __restrict__ Wih1,
                            const float* __restrict__ bih0, const float* __restrict__ bhh0,
                            const float* __restrict__ bih1, const float* __restrict__ bhh1,
                            const float* __restrict__ h0)
{
    size_t stride = (size_t)gridDim.x * blockDim.x;
    size_t tid0 = (size_t)blockIdx.x * blockDim.x + threadIdx.x;

    for (size_t s = tid0; s < (size_t)Gv * Hv; s += stride) {
        int row = (int)(s >> 10);
        int k   = (int)(s & 1023);
        int q = row >> 10;
        int j = row & 1023;
        size_t bdst = (size_t)(4 * j + q) * Hv + k;

        float v = Whh0[s];
        __half hi = __float2half_rn(v);
        g_W0h[bdst] = hi;
        g_W0l[bdst] = __float2half_rn(v - __half2float(hi));

        v = Whh1[s];
        hi = __float2half_rn(v);
        g_W1h[bdst] = hi;
        g_W1l[bdst] = __float2half_rn(v - __half2float(hi));

        v = Wih1[s];
        hi = __float2half_rn(v);
        g_Wfh[bdst] = hi;
        g_Wfl[bdst] = __float2half_rn(v - __half2float(hi));
    }
    for (size_t s = tid0; s < (size_t)Gv * Iv; s += stride) {
        int row = (int)(s >> 7);
        int k   = (int)(s & 127);
        int q = row >> 10;
        int j = row & 1023;
        g_WihT0[(size_t)k * Gv + 4 * j + q] = Wih0[s];
    }
    for (size_t s = tid0; s < (size_t)Gv; s += stride) {
        int q = (int)(s >> 10);
        int j = (int)(s & 1023);
        g_bias0[4 * j + q] = bih0[s] + bhh0[s];
        g_bias1[4 * j + q] = bih1[s] + bhh1[s];
    }
    for (size_t s = tid0; s < (size_t)2 * Bv * Hv; s += stride) {
        g_h0s[s] = __float2half_rn(h0[s]);
    }
}

// ---------------------------------------------------------------------------
// proj0: x[32768,128] @ WihT0 -> g_xg (FFMA path, small)
// ---------------------------------------------------------------------------
__global__ void proj0_kernel(const float* __restrict__ A)
{
    const float* __restrict__ WT   = g_WihT0;
    const float* __restrict__ bias = g_bias0;

    __shared__ float sA[64][17];

    int g0  = blockIdx.x * 128;
    int bt0 = blockIdx.y * 64;
    int tx = threadIdx.x & 31;
    int ty = threadIdx.x >> 5;

    unsigned long long a01[8], a23[8];
#pragma unroll
    for (int r = 0; r < 8; r++) { a01[r] = 0ull; a23[r] = 0ull; }

    const float* wp = WT + (size_t)g0 + 4 * tx;

    for (int k0 = 0; k0 < Iv; k0 += 16) {
        __syncthreads();
#pragma unroll
        for (int e = 0; e < 4; e++) {
            int lin = threadIdx.x + 256 * e;
            int r  = lin >> 4;
            int kk = lin & 15;
            sA[r][kk] = A[(size_t)(bt0 + r) * Iv + k0 + kk];
        }
        __syncthreads();
#pragma unroll
        for (int kk = 0; kk < 16; kk++) {
            ulonglong2 w = *(const ulonglong2*)(wp + (size_t)(k0 + kk) * Gv);
#pragma unroll
            for (int r = 0; r < 8; r++) {
                unsigned long long da = f2dup(sA[ty * 8 + r][kk]);
                ffma2(a01[r], w.x, da);
                ffma2(a23[r], w.y, da);
            }
        }
    }

    float4 bv = *(const float4*)&bias[g0 + 4 * tx];
#pragma unroll
    for (int r = 0; r < 8; r++) {
        float2 p01 = f2unpk(a01[r]);
        float2 p23 = f2unpk(a23[r]);
        float4 o;
        o.x = p01.x + bv.x;
        o.y = p01.y + bv.y;
        o.z = p23.x + bv.z;
        o.w = p23.y + bv.w;
        *(float4*)&g_xg[(size_t)(bt0 + ty * 8 + r) * Gv + g0 + 4 * tx] = o;
    }
}

// ---------------------------------------------------------------------------
// proj1 via HMMA fp16, 2-term (A single, W hi/lo). 2 CTAs/SM.
// ---------------------------------------------------------------------------
#define PJ_KC 32
#define PJ_NCHUNK (Hv / PJ_KC)
#define PJ_ROWB 80
#define PJ_MAT  (128 * PJ_ROWB)
#define PJ_STAGE (3 * PJ_MAT)        // A | Bh | Bl = 30720 B
#define PJ_SMEM  (2 * PJ_STAGE)      // 61440 B

__device__ __forceinline__ void pj_load_chunk(unsigned sbase, int bt0, int n0, int k0, int tid)
{
#pragma unroll
    for (int i = 0; i < 6; i++) {
        int u = tid + 256 * i;       // 0..1535
        int mat = u >> 9;            // 0..2
        int rr  = (u >> 2) & 127;
        int cc  = u & 3;
        unsigned dst = sbase + mat * PJ_MAT + rr * PJ_ROWB + cc * 16;
        const __half* src;
        if      (mat == 0) src = g_h1f + (size_t)(bt0 + rr) * Hv + k0 + cc * 8;
        else if (mat == 1) src = g_Wfh + (size_t)(n0  + rr) * Hv + k0 + cc * 8;
        else               src = g_Wfl + (size_t)(n0  + rr) * Hv + k0 + cc * 8;
        cp16(dst, src);
    }
}

__global__ void __launch_bounds__(256, 2)
proj1_mma_kernel()
{
    extern __shared__ char dsm[];
    unsigned sb0 = smem_u32(dsm);

    __shared__ float s_bias[128];

    int tid  = threadIdx.x;
    int lane = tid & 31;
    int w    = tid >> 5;
    int wm   = w & 1;
    int wn   = w >> 1;
    int n0   = blockIdx.x * 128;
    int bt0  = blockIdx.y * 128;

    for (int i = tid; i < 128; i += 256) s_bias[i] = g_bias1[n0 + i];

    float acc[4][4][4];
#pragma unroll
    for (int mf = 0; mf < 4; mf++)
#pragma unroll
        for (int nf = 0; nf < 4; nf++)
#pragma unroll
            for (int e = 0; e < 4; e++) acc[mf][nf][e] = 0.f;

    unsigned aoff = (unsigned)((64 * wm + (lane & 15)) * PJ_ROWB + ((lane & 16) ? 16 : 0));
    int rl = lane & 15;
    unsigned boff = (unsigned)((32 * wn + (rl & 7)) * PJ_ROWB + ((rl & 8) ? 16 : 0));

    pj_load_chunk(sb0,            bt0, n0, 0,     tid); CP_COMMIT();
    pj_load_chunk(sb0 + PJ_STAGE, bt0, n0, PJ_KC, tid); CP_COMMIT();

    for (int c = 0; c < PJ_NCHUNK; c++) {
        unsigned sb = sb0 + (c & 1) * PJ_STAGE;
        if (c < PJ_NCHUNK - 1) { CP_WAIT1(); } else { CP_WAIT0(); }
        __syncthreads();

#pragma unroll
        for (int ks = 0; ks < 2; ks++) {
            unsigned kb = (unsigned)(ks * 32);
            unsigned Ah[4][4], Bh[4][2], Bl[4][2];
#pragma unroll
            for (int mf = 0; mf < 4; mf++)
                ldm_x4(Ah[mf], sb + aoff + kb + (unsigned)(16 * mf * PJ_ROWB));
#pragma unroll
            for (int nf = 0; nf < 4; nf++) {
                unsigned rb = sb + PJ_MAT + boff + kb + (unsigned)(8 * nf * PJ_ROWB);
                ldm_x2(Bh[nf], rb);
                ldm_x2(Bl[nf], rb + PJ_MAT);
            }
#pragma unroll
            for (int mf = 0; mf < 4; mf++)
#pragma unroll
                for (int nf = 0; nf < 4; nf++) {
                    mma16816f(acc[mf][nf], Ah[mf], Bh[nf]);
                    mma16816f(acc[mf][nf], Ah[mf], Bl[nf]);
                }
        }

        __syncthreads();
        if (c + 2 < PJ_NCHUNK) {
            pj_load_chunk(sb, bt0, n0, (c + 2) * PJ_KC, tid);
            CP_COMMIT();
        }
    }

    int mrow = bt0 + 64 * wm + (lane >> 2);
    int ncol = 32 * wn + 2 * (lane & 3);
#pragma unroll
    for (int mf = 0; mf < 4; mf++) {
#pragma unroll
        for (int nf = 0; nf < 4; nf++) {
            int cc = ncol + 8 * nf;
            float b0 = s_bias[cc], b1 = s_bias[cc + 1];
            float* p0 = &g_xg[(size_t)(mrow + 16 * mf) * Gv + n0 + cc];
            float* p1 = &g_xg[(size_t)(mrow + 16 * mf + 8) * Gv + n0 + cc];
            *(float2*)p0 = make_float2(acc[mf][nf][0] + b0, acc[mf][nf][1] + b1);
            *(float2*)p1 = make_float2(acc[mf][nf][2] + b0, acc[mf][nf][3] + b1);
        }
    }
}

// ---------------------------------------------------------------------------
// Persistent recurrence via fp16 HMMA, 2-term, register-resident epilogue.
// 128 CTAs x 256 threads. CTA: 32 gate cols (8 j), W stationary fp16 hi/lo.
// Per step: M=64 x N=32, K=1024 in 16x64 chunks, 4-stage cp.async pipeline.
// SMEM map (bytes):
//   0       sWh [32][1032 f16] (pitch 2064)
//   66048   sWl
//   132096  sA stages 0..3, each [64][72 f16] (9216 B)
// total 168960
// ---------------------------------------------------------------------------
#define LW_PITCHB 2064
#define LA_PITCHB 144
#define LA_STAGEB 9216
#define LS_SMEM   168960

__device__ __forceinline__ void la_load(unsigned dst, const __half* hsrc,
                                        size_t hstr, int k0, int tid)
{
#pragma unroll
    for (int i = 0; i < 2; i++) {
        int u = tid + 256 * i;       // 0..511
        int rr = u >> 3;             // 0..63
        int cc = u & 7;
        cp16(dst + rr * LA_PITCHB + cc * 16, hsrc + (size_t)rr * hstr + k0 + cc * 8);
    }
}

__global__ void __launch_bounds__(256, 1)
lstm_mma_kernel(int layer, const float* __restrict__ c0l)
{
    extern __shared__ char sm[];
    unsigned sb = smem_u32(sm);

    const __half* __restrict__ Wh = layer ? g_W1h : g_W0h;
    const __half* __restrict__ Wl = layer ? g_W1l : g_W0l;
    __half* __restrict__ seqf     = layer ? g_h2f : g_h1f;

    int tid  = threadIdx.x;
    int lane = tid & 31;
    int w    = tid >> 5;
    int n0   = blockIdx.x * 32;
    int j0   = blockIdx.x * 8;

    // one-time W load (hi/lo)
    {
        const unsigned* srcH = (const unsigned*)(Wh + (size_t)n0 * Hv);
        const unsigned* srcL = (const unsigned*)(Wl + (size_t)n0 * Hv);
        unsigned* dH = (unsigned*)sm;
        unsigned* dL = (unsigned*)(sm + 66048);
        for (int i = tid; i < 32 * 512; i += 256) {
            int r = i >> 9, cc = i & 511;
            dH[r * 516 + cc] = srcH[r * 512 + cc];
            dL[r * 516 + cc] = srcL[r * 512 + cc];
        }
    }
    __syncthreads();

    int wm = w & 1, wn = w >> 1;
    int jl = 2 * wn + ((lane & 3) >> 1);      // local j owned by this thread
    bool evn = ((lane & 1) == 0);

    // cell state: 4 cells per thread: b = 32wm + 16mf + (lane>>2) + 8rr
    float c_[4];
#pragma unroll
    for (int mf = 0; mf < 2; mf++)
#pragma unroll
        for (int rr = 0; rr < 2; rr++) {
            int b = 32 * wm + 16 * mf + (lane >> 2) + 8 * rr;
            c_[mf * 2 + rr] = c0l[(size_t)b * Hv + j0 + jl];
        }

    unsigned aoff  = (unsigned)((32 * wm + (lane & 15)) * LA_PITCHB + ((lane & 16) ? 16 : 0));
    int rl = lane & 15;
    unsigned boffH = sb + (unsigned)((8 * wn + (rl & 7)) * LW_PITCHB + ((rl & 8) ? 16 : 0));
    unsigned boffL = boffH + 66048;
    unsigned sAb = sb + 132096;

    unsigned lg = g_bar_gen;

    for (int t = 0; t < Tv; t++) {
        const __half* hsrc;
        size_t hstr;
        if (t == 0) {
            hsrc = g_h0s + layer * (Bv * Hv);
            hstr = Hv;
        } else {
            hsrc = seqf + (size_t)(t - 1) * Hv;
            hstr = (size_t)Tv * Hv;
        }

        // prologue: 3 chunks in flight
        la_load(sAb,                 hsrc, hstr, 0,   tid); CP_COMMIT();
        la_load(sAb + LA_STAGEB,     hsrc, hstr, 64,  tid); CP_COMMIT();
        la_load(sAb + 2 * LA_STAGEB, hsrc, hstr, 128, tid); CP_COMMIT();

        // prefetch xg for this thread's 4 cells
        float4 xgv[4];
#pragma unroll
        for (int mf = 0; mf < 2; mf++)
#pragma unroll
            for (int rr = 0; rr < 2; rr++) {
                int b = 32 * wm + 16 * mf + (lane >> 2) + 8 * rr;
                xgv[mf * 2 + rr] = *(const float4*)&g_xg[((size_t)b * Tv + t) * Gv + n0 + 4 * jl];
            }

        float acc[2][4];
#pragma unroll
        for (int mf = 0; mf < 2; mf++)
#pragma unroll
            for (int e = 0; e < 4; e++) acc[mf][e] = 0.f;

        for (int ch = 0; ch < 16; ch++) {
            unsigned ab = sAb + (ch & 3) * LA_STAGEB;
            if (ch <= 13)      { CP_WAIT2(); }
            else if (ch == 14) { CP_WAIT1(); }
            else               { CP_WAIT0(); }
            __syncthreads();

            if (ch + 3 < 16) {
                la_load(sAb + ((ch + 3) & 3) * LA_STAGEB, hsrc, hstr, (ch + 3) * 64, tid);
                CP_COMMIT();
            }

#pragma unroll
            for (int ks = 0; ks < 4; ks++) {
                unsigned kb = (unsigned)(ks * 32);
                unsigned wkb = (unsigned)((ch * 64 + ks * 16) * 2);
                unsigned Ah[2][4], Bh[2], Bl[2];
#pragma unroll
                for (int mf = 0; mf < 2; mf++)
                    ldm_x4(Ah[mf], ab + aoff + kb + (unsigned)(16 * mf * LA_PITCHB));
                ldm_x2(Bh, boffH + wkb);
                ldm_x2(Bl, boffL + wkb);
#pragma unroll
                for (int mf = 0; mf < 2; mf++) {
                    mma16816f(acc[mf], Ah[mf], Bh);
                    mma16816f(acc[mf], Ah[mf], Bl);
                }
            }
        }

        // register epilogue: pair lanes exchange (i,f)<->(g,o)
        float pr[2][4];
#pragma unroll
        for (int mf = 0; mf < 2; mf++)
#pragma unroll
            for (int e = 0; e < 4; e++)
                pr[mf][e] = __shfl_xor_sync(0xFFFFFFFFu, acc[mf][e], 1);

#pragma unroll
        for (int mf = 0; mf < 2; mf++) {
#pragma unroll
            for (int rr = 0; rr < 2; rr++) {
                int ci = mf * 2 + rr;
                int b = 32 * wm + 16 * mf + (lane >> 2) + 8 * rr;
                float iv, fv, gv, ov;
                if (evn) { iv = acc[mf][2 * rr]; fv = acc[mf][2 * rr + 1];
                           gv = pr[mf][2 * rr];  ov = pr[mf][2 * rr + 1]; }
                else     { iv = pr[mf][2 * rr];  fv = pr[mf][2 * rr + 1];
                           gv = acc[mf][2 * rr]; ov = acc[mf][2 * rr + 1]; }
                float4 xg = xgv[ci];
                float i_ = sigf(iv + xg.x);
                float f_ = sigf(fv + xg.y);
                float g_ = tanhf(gv + xg.z);
                float o_ = sigf(ov + xg.w);
                float c = f_ * c_[ci] + i_ * g_;
                c_[ci] = c;
                float h = o_ * tanhf(c);
                if (evn) {
                    size_t idx = ((size_t)b * Tv + t) * Hv + j0 + jl;
                    seqf[idx] = __float2half_rn(h);
                    if (layer) g_h2[idx] = h;
                }
            }
        }

        if (t != Tv - 1) grid_barrier(lg);
    }
}

// ---------------------------------------------------------------------------
// Final FC
// ---------------------------------------------------------------------------
__global__ void fc_kernel(const float* __restrict__ Wfc, const float* __restrict__ bfc,
                          float* __restrict__ out)
{
    int bt = blockIdx.x * 8 + (threadIdx.x >> 5);
    int lane = threadIdx.x & 31;
    const float* hrow = g_h2 + (size_t)bt * Hv;
    float s = 0.f;
#pragma unroll 8
    for (int k = lane; k < Hv; k += 32) s += hrow[k] * Wfc[k];
#pragma unroll
    for (int off = 16; off; off >>= 1) s += __shfl_down_sync(0xFFFFFFFFu, s, off);
    if (lane == 0) out[bt] = s + bfc[0];
}

// ---------------------------------------------------------------------------
// Launch (6 graph nodes)
// ---------------------------------------------------------------------------
extern "C" void kernel_launch(void* const* d_in, const int* in_sizes, int n_in,
                              void* d_out, int out_size)
{
    (void)in_sizes; (void)n_in; (void)out_size;
    const float* x    = (const float*)d_in[0];
    const float* h0   = (const float*)d_in[1];
    const float* c0   = (const float*)d_in[2];
    const float* Wih0 = (const float*)d_in[3];
    const float* Whh0 = (const float*)d_in[4];
    const float* bih0 = (const float*)d_in[5];
    const float* bhh0 = (const float*)d_in[6];
    const float* Wih1 = (const float*)d_in[7];
    const float* Whh1 = (const float*)d_in[8];
    const float* bih1 = (const float*)d_in[9];
    const float* bhh1 = (const float*)d_in[10];
    const float* Wfc  = (const float*)d_in[11];
    const float* bfc  = (const float*)d_in[12];
    float* out = (float*)d_out;

    cudaFuncSetAttribute(lstm_mma_kernel,
                         cudaFuncAttributeMaxDynamicSharedMemorySize, LS_SMEM);
    cudaFuncSetAttribute(proj1_mma_kernel,
                         cudaFuncAttributeMaxDynamicSharedMemorySize, PJ_SMEM);

    prep_kernel<<<2048, 256>>>(Whh0, Whh1, Wih0, Wih1, bih0, bhh0, bih1, bhh1, h0);

    // Layer 0
    proj0_kernel<<<dim3(Gv / 128, BTv / 64), 256>>>(x);
    lstm_mma_kernel<<<NBLK, 256, LS_SMEM>>>(0, c0);

    // Layer 1
    proj1_mma_kernel<<<dim3(Gv / 128, BTv / 128), 256, PJ_SMEM>>>();
    lstm_mma_kernel<<<NBLK, 256, LS_SMEM>>>(1, c0 + (size_t)Bv * Hv);

    fc_kernel<<<BTv / 8, 256>>>(Wfc, bfc, out);
}

// round 11
// speedup vs baseline: 5.7244x; 1.0596x over previous
#include <cuda_runtime.h>
#include <cuda_fp16.h>
#include <math.h>

// Problem dims
#define Bv 64
#define Tv 512
#define Iv 128
#define Hv 1024
#define Gv 4096          // 4*H
#define BTv (Bv*Tv)      // 32768

#define NBLK 128         // persistent CTAs for recurrence

// ---------------------------------------------------------------------------
// Static device scratch
// ---------------------------------------------------------------------------
__device__ float g_xg[(size_t)BTv * Gv];       // [B,T,4H] gate pre-activations
__device__ float g_h2[(size_t)BTv * Hv];       // layer-1 output fp32 (for fc)
__device__ float g_bias0[Gv];
__device__ float g_bias1[Gv];

// fp16 activations
__device__ __half g_xf[(size_t)BTv * Iv];      // x in fp16
__device__ __half g_h1f[(size_t)BTv * Hv];
__device__ __half g_h2f[(size_t)BTv * Hv];

// fp16 hi/lo weights, [c = 4j+q][k] layout
__device__ __half g_Wi0h[(size_t)Gv * Iv];     // W_ih0
__device__ __half g_Wi0l[(size_t)Gv * Iv];
__device__ __half g_Wfh[(size_t)Gv * Hv];      // W_ih1
__device__ __half g_Wfl[(size_t)Gv * Hv];
__device__ __half g_W0h[(size_t)Gv * Hv];      // W_hh0
__device__ __half g_W0l[(size_t)Gv * Hv];
__device__ __half g_W1h[(size_t)Gv * Hv];      // W_hh1
__device__ __half g_W1l[(size_t)Gv * Hv];

// h0 fp16: [2][64][1024]
__device__ __half g_h0s[2 * Bv * Hv];

// software grid barrier
__device__ unsigned g_bar_count = 0;
__device__ volatile unsigned g_bar_gen = 0;

__device__ __forceinline__ void grid_barrier(unsigned& local_gen)
{
    __threadfence();
    __syncthreads();
    if (threadIdx.x == 0) {
        unsigned gen = local_gen;
        if (atomicAdd(&g_bar_count, 1u) == NBLK - 1) {
            g_bar_count = 0;
            __threadfence();
            g_bar_gen = gen + 1;
        } else {
            while (g_bar_gen == gen) { }
        }
        __threadfence();
    }
    __syncthreads();
    local_gen++;
}

// ---------------------------------------------------------------------------
// HMMA / ldmatrix / cp.async helpers
// ---------------------------------------------------------------------------
__device__ __forceinline__ unsigned smem_u32(const void* p)
{
    unsigned a;
    asm("{ .reg .u64 t; cvta.to.shared.u64 t, %1; cvt.u32.u64 %0, t; }"
        : "=r"(a) : "l"(p));
    return a;
}
__device__ __forceinline__ void ldm_x4(unsigned r[4], unsigned addr)
{
    asm volatile("ldmatrix.sync.aligned.m8n8.x4.shared.b16 {%0,%1,%2,%3}, [%4];"
                 : "=r"(r[0]), "=r"(r[1]), "=r"(r[2]), "=r"(r[3]) : "r"(addr));
}
__device__ __forceinline__ void ldm_x2(unsigned r[2], unsigned addr)
{
    asm volatile("ldmatrix.sync.aligned.m8n8.x2.shared.b16 {%0,%1}, [%2];"
                 : "=r"(r[0]), "=r"(r[1]) : "r"(addr));
}
__device__ __forceinline__ void mma16816f(float d[4], const unsigned a[4], const unsigned b[2])
{
    asm volatile("mma.sync.aligned.m16n8k16.row.col.f32.f16.f16.f32 "
                 "{%0,%1,%2,%3}, {%4,%5,%6,%7}, {%8,%9}, {%0,%1,%2,%3};"
                 : "+f"(d[0]), "+f"(d[1]), "+f"(d[2]), "+f"(d[3])
                 : "r"(a[0]), "r"(a[1]), "r"(a[2]), "r"(a[3]), "r"(b[0]), "r"(b[1]));
}
__device__ __forceinline__ void cp16(unsigned dst, const void* src)
{
    asm volatile("cp.async.cg.shared.global [%0], [%1], 16;"
                 :: "r"(dst), "l"(src) : "memory");
}
#define CP_COMMIT() asm volatile("cp.async.commit_group;" ::: "memory")
#define CP_WAIT2()  asm volatile("cp.async.wait_group 2;" ::: "memory")
#define CP_WAIT1()  asm volatile("cp.async.wait_group 1;" ::: "memory")
#define CP_WAIT0()  asm volatile("cp.async.wait_group 0;" ::: "memory")

__device__ __forceinline__ float sigf(float v) { return 1.0f / (1.0f + expf(-v)); }

// ---------------------------------------------------------------------------
// Prep: weight transforms (fp16 hi/lo) + x/h0 fp16.
// ---------------------------------------------------------------------------
__global__ void prep_kernel(const float* __restrict__ Whh0, const float* __restrict__ Whh1,
                            const float* __restrict__ Wih0, const float* __restrict__ Wih1,
                            const float* __restrict__ bih0, const float* __restrict__ bhh0,
                            const float* __restrict__ bih1, const float* __restrict__ bhh1,
                            const float* __restrict__ h0,   const float* __restrict__ x)
{
    size_t stride = (size_t)gridDim.x * blockDim.x;
    size_t tid0 = (size_t)blockIdx.x * blockDim.x + threadIdx.x;

    for (size_t s = tid0; s < (size_t)Gv * Hv; s += stride) {
        int row = (int)(s >> 10);
        int k   = (int)(s & 1023);
        int q = row >> 10;
        int j = row & 1023;
        size_t bdst = (size_t)(4 * j + q) * Hv + k;

        float v = Whh0[s];
        __half hi = __float2half_rn(v);
        g_W0h[bdst] = hi;
        g_W0l[bdst] = __float2half_rn(v - __half2float(hi));

        v = Whh1[s];
        hi = __float2half_rn(v);
        g_W1h[bdst] = hi;
        g_W1l[bdst] = __float2half_rn(v - __half2float(hi));

        v = Wih1[s];
        hi = __float2half_rn(v);
        g_Wfh[bdst] = hi;
        g_Wfl[bdst] = __float2half_rn(v - __half2float(hi));
    }
    for (size_t s = tid0; s < (size_t)Gv * Iv; s += stride) {
        int row = (int)(s >> 7);
        int k   = (int)(s & 127);
        int q = row >> 10;
        int j = row & 1023;
        size_t bdst = (size_t)(4 * j + q) * Iv + k;
        float v = Wih0[s];
        __half hi = __float2half_rn(v);
        g_Wi0h[bdst] = hi;
        g_Wi0l[bdst] = __float2half_rn(v - __half2float(hi));
    }
    for (size_t s = tid0; s < (size_t)Gv; s += stride) {
        int q = (int)(s >> 10);
        int j = (int)(s & 1023);
        g_bias0[4 * j + q] = bih0[s] + bhh0[s];
        g_bias1[4 * j + q] = bih1[s] + bhh1[s];
    }
    for (size_t s = tid0; s < (size_t)2 * Bv * Hv; s += stride) {
        g_h0s[s] = __float2half_rn(h0[s]);
    }
    for (size_t s = tid0; s < (size_t)BTv * Iv; s += stride) {
        g_xf[s] = __float2half_rn(x[s]);
    }
}

// ---------------------------------------------------------------------------
// Projection GEMM via fp16 HMMA (A single, W hi/lo). Template K (compile-time
// constants everywhere — byte-faithful to the proven round-9 K=1024 kernel).
// CTA: 128 bt x 128 gate cols. K chunked by 32, 2-stage cp.async pipeline.
// ---------------------------------------------------------------------------
#define PJ_ROWB 80
#define PJ_MAT  (128 * PJ_ROWB)
#define PJ_STAGE (3 * PJ_MAT)        // A | Bh | Bl = 30720 B
#define PJ_SMEM  (2 * PJ_STAGE)      // 61440 B

template <int K>
__device__ __forceinline__ void pj_load_chunk(unsigned sbase, int bt0, int n0, int k0, int tid)
{
    const __half* __restrict__ A  = (K == Iv) ? g_xf   : g_h1f;
    const __half* __restrict__ Bh = (K == Iv) ? g_Wi0h : g_Wfh;
    const __half* __restrict__ Bl = (K == Iv) ? g_Wi0l : g_Wfl;
#pragma unroll
    for (int i = 0; i < 6; i++) {
        int u = tid + 256 * i;       // 0..1535
        int mat = u >> 9;            // 0..2
        int rr  = (u >> 2) & 127;
        int cc  = u & 3;
        unsigned dst = sbase + mat * PJ_MAT + rr * PJ_ROWB + cc * 16;
        const __half* src;
        if      (mat == 0) src = A  + (size_t)(bt0 + rr) * K + k0 + cc * 8;
        else if (mat == 1) src = Bh + (size_t)(n0  + rr) * K + k0 + cc * 8;
        else               src = Bl + (size_t)(n0  + rr) * K + k0 + cc * 8;
        cp16(dst, src);
    }
}

template <int K>
__global__ void __launch_bounds__(256, 2)
proj_mma_kernel()
{
    extern __shared__ char dsm[];
    unsigned sb0 = smem_u32(dsm);

    __shared__ float s_bias[128];

    const float* __restrict__ bias = (K == Iv) ? g_bias0 : g_bias1;
    const int NCHUNK = K / 32;

    int tid  = threadIdx.x;
    int lane = tid & 31;
    int w    = tid >> 5;
    int wm   = w & 1;
    int wn   = w >> 1;
    int n0   = blockIdx.x * 128;
    int bt0  = blockIdx.y * 128;

    for (int i = tid; i < 128; i += 256) s_bias[i] = bias[n0 + i];

    float acc[4][4][4];
#pragma unroll
    for (int mf = 0; mf < 4; mf++)
#pragma unroll
        for (int nf = 0; nf < 4; nf++)
#pragma unroll
            for (int e = 0; e < 4; e++) acc[mf][nf][e] = 0.f;

    unsigned aoff = (unsigned)((64 * wm + (lane & 15)) * PJ_ROWB + ((lane & 16) ? 16 : 0));
    int rl = lane & 15;
    unsigned boff = (unsigned)((32 * wn + (rl & 7)) * PJ_ROWB + ((rl & 8) ? 16 : 0));

    pj_load_chunk<K>(sb0,            bt0, n0, 0,  tid); CP_COMMIT();
    pj_load_chunk<K>(sb0 + PJ_STAGE, bt0, n0, 32, tid); CP_COMMIT();

    for (int c = 0; c < NCHUNK; c++) {
        unsigned sb = sb0 + (c & 1) * PJ_STAGE;
        if (c < NCHUNK - 1) { CP_WAIT1(); } else { CP_WAIT0(); }
        __syncthreads();

#pragma unroll
        for (int ks = 0; ks < 2; ks++) {
            unsigned kb = (unsigned)(ks * 32);
            unsigned Ahf[4][4], Bhf[4][2], Blf[4][2];
#pragma unroll
            for (int mf = 0; mf < 4; mf++)
                ldm_x4(Ahf[mf], sb + aoff + kb + (unsigned)(16 * mf * PJ_ROWB));
#pragma unroll
            for (int nf = 0; nf < 4; nf++) {
                unsigned rb = sb + PJ_MAT + boff + kb + (unsigned)(8 * nf * PJ_ROWB);
                ldm_x2(Bhf[nf], rb);
                ldm_x2(Blf[nf], rb + PJ_MAT);
            }
#pragma unroll
            for (int mf = 0; mf < 4; mf++)
#pragma unroll
                for (int nf = 0; nf < 4; nf++) {
                    mma16816f(acc[mf][nf], Ahf[mf], Bhf[nf]);
                    mma16816f(acc[mf][nf], Ahf[mf], Blf[nf]);
                }
        }

        __syncthreads();
        if (c + 2 < NCHUNK) {
            pj_load_chunk<K>(sb, bt0, n0, (c + 2) * 32, tid);
            CP_COMMIT();
        }
    }

    int mrow = bt0 + 64 * wm + (lane >> 2);
    int ncol = 32 * wn + 2 * (lane & 3);
#pragma unroll
    for (int mf = 0; mf < 4; mf++) {
#pragma unroll
        for (int nf = 0; nf < 4; nf++) {
            int cc = ncol + 8 * nf;
            float b0 = s_bias[cc], b1 = s_bias[cc + 1];
            float* p0 = &g_xg[(size_t)(mrow + 16 * mf) * Gv + n0 + cc];
            float* p1 = &g_xg[(size_t)(mrow + 16 * mf + 8) * Gv + n0 + cc];
            *(float2*)p0 = make_float2(acc[mf][nf][0] + b0, acc[mf][nf][1] + b1);
            *(float2*)p1 = make_float2(acc[mf][nf][2] + b0, acc[mf][nf][3] + b1);
        }
    }
}

// ---------------------------------------------------------------------------
// Persistent recurrence via fp16 HMMA — EXACT round-9 structure (64-k chunks,
// pitch 144, 4-stage pipeline, register epilogue) + split Bh/Bl accumulators.
// SMEM map (bytes):
//   0       sWh [32][1032 f16] (pitch 2064)
//   66048   sWl
//   132096  sA stages 0..3, each [64][72 f16] (9216 B)
// total 168960
// ---------------------------------------------------------------------------
#define LW_PITCHB 2064
#define LA_PITCHB 144
#define LA_STAGEB 9216
#define LS_SMEM   168960

__device__ __forceinline__ void la_load(unsigned dst, const __half* hsrc,
                                        size_t hstr, int k0, int tid)
{
#pragma unroll
    for (int i = 0; i < 2; i++) {
        int u = tid + 256 * i;       // 0..511
        int rr = u >> 3;             // 0..63
        int cc = u & 7;
        cp16(dst + rr * LA_PITCHB + cc * 16, hsrc + (size_t)rr * hstr + k0 + cc * 8);
    }
}

__global__ void __launch_bounds__(256, 1)
lstm_mma_kernel(int layer, const float* __restrict__ c0l)
{
    extern __shared__ char sm[];
    unsigned sb = smem_u32(sm);

    const __half* __restrict__ Wh = layer ? g_W1h : g_W0h;
    const __half* __restrict__ Wl = layer ? g_W1l : g_W0l;
    __half* __restrict__ seqf     = layer ? g_h2f : g_h1f;

    int tid  = threadIdx.x;
    int lane = tid & 31;
    int w    = tid >> 5;
    int n0   = blockIdx.x * 32;
    int j0   = blockIdx.x * 8;

    // one-time W load (hi/lo)
    {
        const unsigned* srcH = (const unsigned*)(Wh + (size_t)n0 * Hv);
        const unsigned* srcL = (const unsigned*)(Wl + (size_t)n0 * Hv);
        unsigned* dH = (unsigned*)sm;
        unsigned* dL = (unsigned*)(sm + 66048);
        for (int i = tid; i < 32 * 512; i += 256) {
            int r = i >> 9, cc = i & 511;
            dH[r * 516 + cc] = srcH[r * 512 + cc];
            dL[r * 516 + cc] = srcL[r * 512 + cc];
        }
    }
    __syncthreads();

    int wm = w & 1, wn = w >> 1;
    int jl = 2 * wn + ((lane & 3) >> 1);
    bool evn = ((lane & 1) == 0);

    float c_[4];
#pragma unroll
    for (int mf = 0; mf < 2; mf++)
#pragma unroll
        for (int rr = 0; rr < 2; rr++) {
            int b = 32 * wm + 16 * mf + (lane >> 2) + 8 * rr;
            c_[mf * 2 + rr] = c0l[(size_t)b * Hv + j0 + jl];
        }

    unsigned aoff  = (unsigned)((32 * wm + (lane & 15)) * LA_PITCHB + ((lane & 16) ? 16 : 0));
    int rl = lane & 15;
    unsigned boffH = sb + (unsigned)((8 * wn + (rl & 7)) * LW_PITCHB + ((rl & 8) ? 16 : 0));
    unsigned boffL = boffH + 66048;
    unsigned sAb = sb + 132096;

    unsigned lg = g_bar_gen;

    for (int t = 0; t < Tv; t++) {
        const __half* hsrc;
        size_t hstr;
        if (t == 0) {
            hsrc = g_h0s + layer * (Bv * Hv);
            hstr = Hv;
        } else {
            hsrc = seqf + (size_t)(t - 1) * Hv;
            hstr = (size_t)Tv * Hv;
        }

        // prologue: 3 chunks in flight
        la_load(sAb,                 hsrc, hstr, 0,   tid); CP_COMMIT();
        la_load(sAb + LA_STAGEB,     hsrc, hstr, 64,  tid); CP_COMMIT();
        la_load(sAb + 2 * LA_STAGEB, hsrc, hstr, 128, tid); CP_COMMIT();

        float4 xgv[4];
#pragma unroll
        for (int mf = 0; mf < 2; mf++)
#pragma unroll
            for (int rr = 0; rr < 2; rr++) {
                int b = 32 * wm + 16 * mf + (lane >> 2) + 8 * rr;
                xgv[mf * 2 + rr] = *(const float4*)&g_xg[((size_t)b * Tv + t) * Gv + n0 + 4 * jl];
            }

        float accH[2][4], accL[2][4];
#pragma unroll
        for (int mf = 0; mf < 2; mf++)
#pragma unroll
            for (int e = 0; e < 4; e++) { accH[mf][e] = 0.f; accL[mf][e] = 0.f; }

        for (int ch = 0; ch < 16; ch++) {
            unsigned ab = sAb + (ch & 3) * LA_STAGEB;
            if (ch <= 13)      { CP_WAIT2(); }
            else if (ch == 14) { CP_WAIT1(); }
            else               { CP_WAIT0(); }
            __syncthreads();

            if (ch + 3 < 16) {
                la_load(sAb + ((ch + 3) & 3) * LA_STAGEB, hsrc, hstr, (ch + 3) * 64, tid);
                CP_COMMIT();
            }

#pragma unroll
            for (int ks = 0; ks < 4; ks++) {
                unsigned kb = (unsigned)(ks * 32);
                unsigned wkb = (unsigned)((ch * 64 + ks * 16) * 2);
                unsigned Ahf[2][4], Bhf[2], Blf[2];
#pragma unroll
                for (int mf = 0; mf < 2; mf++)
                    ldm_x4(Ahf[mf], ab + aoff + kb + (unsigned)(16 * mf * LA_PITCHB));
                ldm_x2(Bhf, boffH + wkb);
                ldm_x2(Blf, boffL + wkb);
#pragma unroll
                for (int mf = 0; mf < 2; mf++) {
                    mma16816f(accH[mf], Ahf[mf], Bhf);
                    mma16816f(accL[mf], Ahf[mf], Blf);
                }
            }
        }

        // combine hi/lo accumulators
        float acc[2][4];
#pragma unroll
        for (int mf = 0; mf < 2; mf++)
#pragma unroll
            for (int e = 0; e < 4; e++) acc[mf][e] = accH[mf][e] + accL[mf][e];

        // register epilogue: pair lanes exchange (i,f)<->(g,o)
        float pr[2][4];
#pragma unroll
        for (int mf = 0; mf < 2; mf++)
#pragma unroll
            for (int e = 0; e < 4; e++)
                pr[mf][e] = __shfl_xor_sync(0xFFFFFFFFu, acc[mf][e], 1);

#pragma unroll
        for (int mf = 0; mf < 2; mf++) {
#pragma unroll
            for (int rr = 0; rr < 2; rr++) {
                int ci = mf * 2 + rr;
                int b = 32 * wm + 16 * mf + (lane >> 2) + 8 * rr;
                float iv, fv, gv, ov;
                if (evn) { iv = acc[mf][2 * rr]; fv = acc[mf][2 * rr + 1];
                           gv = pr[mf][2 * rr];  ov = pr[mf][2 * rr + 1]; }
                else     { iv = pr[mf][2 * rr];  fv = pr[mf][2 * rr + 1];
                           gv = acc[mf][2 * rr]; ov = acc[mf][2 * rr + 1]; }
                float4 xg = xgv[ci];
                float i_ = sigf(iv + xg.x);
                float f_ = sigf(fv + xg.y);
                float g_ = tanhf(gv + xg.z);
                float o_ = sigf(ov + xg.w);
                float c = f_ * c_[ci] + i_ * g_;
                c_[ci] = c;
                float h = o_ * tanhf(c);
                if (evn) {
                    size_t idx = ((size_t)b * Tv + t) * Hv + j0 + jl;
                    seqf[idx] = __float2half_rn(h);
                    if (layer) g_h2[idx] = h;
                }
            }
        }

        if (t != Tv - 1) grid_barrier(lg);
    }
}

// ---------------------------------------------------------------------------
// Final FC
// ---------------------------------------------------------------------------
__global__ void fc_kernel(const float* __restrict__ Wfc, const float* __restrict__ bfc,
                          float* __restrict__ out)
{
    int bt = blockIdx.x * 8 + (threadIdx.x >> 5);
    int lane = threadIdx.x & 31;
    const float* hrow = g_h2 + (size_t)bt * Hv;
    float s = 0.f;
#pragma unroll 8
    for (int k = lane; k < Hv; k += 32) s += hrow[k] * Wfc[k];
#pragma unroll
    for (int off = 16; off; off >>= 1) s += __shfl_down_sync(0xFFFFFFFFu, s, off);
    if (lane == 0) out[bt] = s + bfc[0];
}

// ---------------------------------------------------------------------------
// Launch (6 graph nodes)
// ---------------------------------------------------------------------------
extern "C" void kernel_launch(void* const* d_in, const int* in_sizes, int n_in,
                              void* d_out, int out_size)
{
    (void)in_sizes; (void)n_in; (void)out_size;
    const float* x    = (const float*)d_in[0];
    const float* h0   = (const float*)d_in[1];
    const float* c0   = (const float*)d_in[2];
    const float* Wih0 = (const float*)d_in[3];
    const float* Whh0 = (const float*)d_in[4];
    const float* bih0 = (const float*)d_in[5];
    const float* bhh0 = (const float*)d_in[6];
    const float* Wih1 = (const float*)d_in[7];
    const float* Whh1 = (const float*)d_in[8];
    const float* bih1 = (const float*)d_in[9];
    const float* bhh1 = (const float*)d_in[10];
    const float* Wfc  = (const float*)d_in[11];
    const float* bfc  = (const float*)d_in[12];
    float* out = (float*)d_out;

    cudaFuncSetAttribute(lstm_mma_kernel,
                         cudaFuncAttributeMaxDynamicSharedMemorySize, LS_SMEM);
    cudaFuncSetAttribute(proj_mma_kernel<Iv>,
                         cudaFuncAttributeMaxDynamicSharedMemorySize, PJ_SMEM);
    cudaFuncSetAttribute(proj_mma_kernel<Hv>,
                         cudaFuncAttributeMaxDynamicSharedMemorySize, PJ_SMEM);

    prep_kernel<<<2048, 256>>>(Whh0, Whh1, Wih0, Wih1, bih0, bhh0, bih1, bhh1, h0, x);

    // Layer 0: HMMA projection (K=128) + recurrence
    proj_mma_kernel<Iv><<<dim3(Gv / 128, BTv / 128), 256, PJ_SMEM>>>();
    lstm_mma_kernel<<<NBLK, 256, LS_SMEM>>>(0, c0);

    // Layer 1: HMMA projection (K=1024) + recurrence
    proj_mma_kernel<Hv><<<dim3(Gv / 128, BTv / 128), 256, PJ_SMEM>>>();
    lstm_mma_kernel<<<NBLK, 256, LS_SMEM>>>(1, c0 + (size_t)Bv * Hv);

    fc_kernel<<<BTv / 8, 256>>>(Wfc, bfc, out);
}